// round 11
// baseline (speedup 1.0000x reference)
#include <cuda_runtime.h>
#include <cuda_bf16.h>
#include <cstdint>

#define N_NODES 100000
#define N_EDGES 1600000
#define NFEAT   512
#define NHID    256
#define NCLASS  40
#define NF4     (NCLASS / 4)

#define SCAN_T  1024
#define NBLK    ((N_NODES + SCAN_T - 1) / SCAN_T)   // 98

// ---------------- scratch (static device globals; no allocation) ----------------
__device__ float g_h1[(size_t)N_NODES * NHID];   // holds bf16 hi|lo of h1 (aliased)
__device__ float g_h2[(size_t)N_NODES * NHID];   // holds bf16 hi|lo of h2 (aliased)
__device__ float g_h [(size_t)N_NODES * NCLASS];
__device__ float g_vA[(size_t)N_NODES * NCLASS];
__device__ float g_vB[(size_t)N_NODES * NCLASS];
__device__ float g_dinv[N_NODES];
__device__ int   g_cnt [N_NODES];
__device__ int   g_fill[N_NODES];
__device__ int   g_rowstart[N_NODES + 1];
__device__ int   g_cols[N_EDGES];
__device__ int   g_bsum[128];
// pre-split weights (bf16 hi/lo), 16B-aligned
__device__ __align__(16) __nv_bfloat16 g_w1hi[NHID * NFEAT];
__device__ __align__(16) __nv_bfloat16 g_w1lo[NHID * NFEAT];
__device__ __align__(16) __nv_bfloat16 g_w2hi[NHID * NHID];
__device__ __align__(16) __nv_bfloat16 g_w2lo[NHID * NHID];
__device__ __align__(16) __nv_bfloat16 g_w3hi[NCLASS * NHID];
__device__ __align__(16) __nv_bfloat16 g_w3lo[NCLASS * NHID];

// ---------------- helpers ----------------
__device__ __forceinline__ uint32_t smem_u32(const void* p) {
    uint32_t a;
    asm("{ .reg .u64 t; cvta.to.shared.u64 t, %1; cvt.u32.u64 %0, t; }" : "=r"(a) : "l"(p));
    return a;
}

__device__ __forceinline__ void mma16816(float c[4], const uint32_t a[4],
                                         uint32_t b0, uint32_t b1) {
    asm volatile(
        "mma.sync.aligned.m16n8k16.row.col.f32.bf16.bf16.f32 "
        "{%0,%1,%2,%3}, {%4,%5,%6,%7}, {%8,%9}, {%0,%1,%2,%3};"
        : "+f"(c[0]), "+f"(c[1]), "+f"(c[2]), "+f"(c[3])
        : "r"(a[0]), "r"(a[1]), "r"(a[2]), "r"(a[3]), "r"(b0), "r"(b1));
}

#define LDSM_X4(r0, r1, r2, r3, addr) \
    asm volatile("ldmatrix.sync.aligned.m8n8.x4.shared.b16 {%0,%1,%2,%3}, [%4];" \
                 : "=r"(r0), "=r"(r1), "=r"(r2), "=r"(r3) : "r"(addr))

__device__ __forceinline__ void cp16(uint32_t dst, const void* src, uint32_t bytes) {
    asm volatile("cp.async.cg.shared.global [%0], [%1], 16, %2;"
                 :: "r"(dst), "l"(src), "r"(bytes));
}
#define CP_COMMIT() asm volatile("cp.async.commit_group;" ::: "memory")
#define CP_WAIT(n)  asm volatile("cp.async.wait_group %0;" :: "n"(n) : "memory")

__device__ __forceinline__ void split4(float4 v, uint2& hi, uint2& lo) {
    __nv_bfloat16 hx = __float2bfloat16(v.x);
    __nv_bfloat16 hy = __float2bfloat16(v.y);
    __nv_bfloat16 hz = __float2bfloat16(v.z);
    __nv_bfloat16 hw = __float2bfloat16(v.w);
    __nv_bfloat16 lx = __float2bfloat16(v.x - __bfloat162float(hx));
    __nv_bfloat16 ly = __float2bfloat16(v.y - __bfloat162float(hy));
    __nv_bfloat16 lz = __float2bfloat16(v.z - __bfloat162float(hz));
    __nv_bfloat16 lw = __float2bfloat16(v.w - __bfloat162float(hw));
    hi.x = ((uint32_t)__bfloat16_as_ushort(hy) << 16) | __bfloat16_as_ushort(hx);
    hi.y = ((uint32_t)__bfloat16_as_ushort(hw) << 16) | __bfloat16_as_ushort(hz);
    lo.x = ((uint32_t)__bfloat16_as_ushort(ly) << 16) | __bfloat16_as_ushort(lx);
    lo.y = ((uint32_t)__bfloat16_as_ushort(lw) << 16) | __bfloat16_as_ushort(lz);
}

__device__ __forceinline__ void split2(float2 v, uint32_t& hi, uint32_t& lo) {
    __nv_bfloat16 hx = __float2bfloat16(v.x);
    __nv_bfloat16 hy = __float2bfloat16(v.y);
    __nv_bfloat16 lx = __float2bfloat16(v.x - __bfloat162float(hx));
    __nv_bfloat16 ly = __float2bfloat16(v.y - __bfloat162float(hy));
    hi = ((uint32_t)__bfloat16_as_ushort(hy) << 16) | __bfloat16_as_ushort(hx);
    lo = ((uint32_t)__bfloat16_as_ushort(ly) << 16) | __bfloat16_as_ushort(lx);
}

// ---------------- graph preprocessing ----------------
__global__ void zero_counts() {
    int i = blockIdx.x * blockDim.x + threadIdx.x;
    if (i < N_NODES) { g_cnt[i] = 0; g_fill[i] = 0; }
}
__global__ void count_deg(const int* __restrict__ rows) {
    int e = blockIdx.x * blockDim.x + threadIdx.x;
    if (e < N_EDGES) atomicAdd(&g_cnt[rows[e]], 1);
}
__global__ void compute_dinv() {
    int i = blockIdx.x * blockDim.x + threadIdx.x;
    if (i < N_NODES) g_dinv[i] = 1.0f / (float)(g_cnt[i] + 1);
}
__global__ void scan_blocks() {
    __shared__ int s[SCAN_T];
    int t   = threadIdx.x;
    int gid = blockIdx.x * SCAN_T + t;
    int v   = (gid < N_NODES) ? g_cnt[gid] : 0;
    s[t] = v;
    __syncthreads();
    #pragma unroll
    for (int off = 1; off < SCAN_T; off <<= 1) {
        int x = (t >= off) ? s[t - off] : 0;
        __syncthreads();
        s[t] += x;
        __syncthreads();
    }
    if (gid < N_NODES) g_rowstart[gid] = s[t] - v;
    if (t == SCAN_T - 1) g_bsum[blockIdx.x] = s[t];
}
__global__ void scan_offsets() {
    if (threadIdx.x == 0 && blockIdx.x == 0) {
        int acc = 0;
        for (int i = 0; i < NBLK; i++) { int t = g_bsum[i]; g_bsum[i] = acc; acc += t; }
        g_rowstart[N_NODES] = acc;
    }
}
__global__ void scan_add() {
    int t   = threadIdx.x;
    int gid = blockIdx.x * SCAN_T + t;
    if (gid < N_NODES) g_rowstart[gid] += g_bsum[blockIdx.x];
}
__global__ void scatter_edges(const int* __restrict__ rows, const int* __restrict__ cols) {
    int e = blockIdx.x * blockDim.x + threadIdx.x;
    if (e < N_EDGES) {
        int r   = rows[e];
        int pos = g_rowstart[r] + atomicAdd(&g_fill[r], 1);
        g_cols[pos] = cols[e];
    }
}
__global__ void split_w(const float* __restrict__ src, __nv_bfloat16* __restrict__ hi,
                        __nv_bfloat16* __restrict__ lo, int n) {
    int i = blockIdx.x * 256 + threadIdx.x;
    if (i < n) {
        float v = src[i];
        __nv_bfloat16 h = __float2bfloat16(v);
        hi[i] = h;
        lo[i] = __float2bfloat16(v - __bfloat162float(h));
    }
}

// ====== HMMA GEMM, bf16 3-term split, K-tile 32, 2-stage cp.async pipeline ======
#define RSB 80             // smem row stride bytes (64B data + 16B pad)

template<int BN, int RELU, int ABF16, int OUTSPLIT>
__global__ __launch_bounds__(256, 2)
void gemm_hmma(const float* __restrict__ Af,
               const __nv_bfloat16* __restrict__ Ahi_g,
               const __nv_bfloat16* __restrict__ Alo_g,
               const __nv_bfloat16* __restrict__ Whi_g,
               const __nv_bfloat16* __restrict__ Wlo_g,
               const float* __restrict__ bias,
               float* __restrict__ C,
               __nv_bfloat16* __restrict__ Chi,
               __nv_bfloat16* __restrict__ Clo,
               int Nrows, int Mcols, int K)
{
    constexpr int NJ      = BN / 16;
    constexpr int ABYTES  = 128 * RSB;                   // 10240
    constexpr int BBYTES  = BN * RSB;
    constexpr int STAGE   = 2 * ABYTES + 2 * BBYTES;     // AHI|ALO|BHI|BLO
    constexpr int OFF_BS  = 2 * STAGE;
    constexpr int BCHUNKS = BN / 64;                     // cp.async 16B iters for B

    extern __shared__ __align__(16) char sm[];

    const uint32_t smb = smem_u32(sm);
    const int tid = threadIdx.x;
    const int wid = tid >> 5;
    const int lid = tid & 31;
    const int warpM = (wid & 3) * 32;
    const int warpN = (wid >> 2) * (BN / 2);
    const int rowBase = blockIdx.y * 128;
    const int colBase = blockIdx.x * BN;
    const int NT = K / 32;

    // bias -> smem
    for (int i = tid; i < BN; i += 256) {
        int gc = colBase + i;
        *(float*)(sm + OFF_BS + i * 4) = (gc < Mcols) ? bias[gc] : 0.0f;
    }

    // per-lane ldmatrix address components
    const int aRow  = (lid & 7) + ((lid >> 3) & 1) * 8;
    const int aColB = (lid >> 4) * 16;
    const int bN    = ((lid >> 4) * 8) + (lid & 7);
    const int bColB = ((lid >> 3) & 1) * 16;

    const uint32_t aAddr0 = smb + (warpM + aRow) * RSB + aColB;
    const uint32_t bAddr0 = smb + 2 * ABYTES + (warpN + bN) * RSB + bColB;

    float acc[2][NJ][4];
    #pragma unroll
    for (int i = 0; i < 2; i++)
        #pragma unroll
        for (int j = 0; j < NJ; j++)
            #pragma unroll
            for (int q = 0; q < 4; q++) acc[i][j][q] = 0.0f;

    float4 paf[4];   // fp32-A prefetch (ABF16=0 only)

    // cp.async A (bf16 path): 128x32 hi + lo, 2 chunks each per thread
    auto cpA = [&](int t, int st) {
        const int kt = t * 32;
        char* base = sm + st * STAGE;
        #pragma unroll
        for (int i = 0; i < 2; i++) {
            int idx = tid + i * 256;
            int row = idx >> 2;
            int c   = idx & 3;
            int gr  = rowBase + row;
            uint32_t sz = (gr < Nrows) ? 16u : 0u;
            int gra = (gr < Nrows) ? gr : 0;
            uint32_t so = smem_u32(base + row * RSB + c * 16);
            cp16(so,          Ahi_g + (size_t)gra * K + kt + c * 8, sz);
            cp16(so + ABYTES, Alo_g + (size_t)gra * K + kt + c * 8, sz);
        }
    };
    // cp.async B: BN x 32 hi + lo
    auto cpB = [&](int t, int st) {
        const int kt = t * 32;
        char* base = sm + st * STAGE + 2 * ABYTES;
        #pragma unroll
        for (int i = 0; i < BCHUNKS; i++) {
            int idx = tid + i * 256;
            int row = idx >> 2;
            int c   = idx & 3;
            int gm  = colBase + row;
            uint32_t sz = (gm < Mcols) ? 16u : 0u;
            int gma = (gm < Mcols) ? gm : 0;
            uint32_t so = smem_u32(base + row * RSB + c * 16);
            cp16(so,          Whi_g + (size_t)gma * K + kt + c * 8, sz);
            cp16(so + BBYTES, Wlo_g + (size_t)gma * K + kt + c * 8, sz);
        }
    };
    // fp32 A prefetch to regs (ABF16=0): 128x32 fp32, 4 float4/thread
    auto ldA = [&](int t) {
        const int kt = t * 32;
        #pragma unroll
        for (int i = 0; i < 4; i++) {
            int idx = tid + i * 256;
            int row = idx >> 3;
            int c4  = idx & 7;
            int gr  = rowBase + row;
            paf[i] = make_float4(0.f, 0.f, 0.f, 0.f);
            if (gr < Nrows) paf[i] = *(const float4*)(Af + (size_t)gr * K + kt + c4 * 4);
        }
    };
    auto stsA = [&](int st) {
        char* base = sm + st * STAGE;
        #pragma unroll
        for (int i = 0; i < 4; i++) {
            int idx = tid + i * 256;
            int row = idx >> 3;
            int c4  = idx & 7;
            uint2 hi, lo; split4(paf[i], hi, lo);
            *(uint2*)(base + row * RSB + c4 * 8) = hi;
            *(uint2*)(base + ABYTES + row * RSB + c4 * 8) = lo;
        }
    };

    auto MMA = [&](int st) {
        const uint32_t aA = aAddr0 + st * STAGE;
        const uint32_t bA = bAddr0 + st * STAGE;
        #pragma unroll
        for (int ks = 0; ks < 2; ks++) {
            const uint32_t kOff = ks * 32;
            uint32_t ah[2][4], al[2][4];
            #pragma unroll
            for (int i = 0; i < 2; i++) {
                uint32_t aa = aA + i * 16 * RSB + kOff;
                LDSM_X4(ah[i][0], ah[i][1], ah[i][2], ah[i][3], aa);
                LDSM_X4(al[i][0], al[i][1], al[i][2], al[i][3], aa + ABYTES);
            }
            #pragma unroll
            for (int jp = 0; jp < NJ / 2; jp++) {
                uint32_t bb = bA + jp * 16 * RSB + kOff;
                uint32_t bh0, bh1, bh2, bh3, bl0, bl1, bl2, bl3;
                LDSM_X4(bh0, bh1, bh2, bh3, bb);
                LDSM_X4(bl0, bl1, bl2, bl3, bb + BBYTES);
                #pragma unroll
                for (int i = 0; i < 2; i++) {
                    mma16816(acc[i][2 * jp],     ah[i], bh0, bh1);
                    mma16816(acc[i][2 * jp],     ah[i], bl0, bl1);
                    mma16816(acc[i][2 * jp],     al[i], bh0, bh1);
                    mma16816(acc[i][2 * jp + 1], ah[i], bh2, bh3);
                    mma16816(acc[i][2 * jp + 1], ah[i], bl2, bl3);
                    mma16816(acc[i][2 * jp + 1], al[i], bh2, bh3);
                }
            }
        }
    };

    // ---- prologue: stage 0 in flight ----
    if (ABF16) cpA(0, 0); else ldA(0);
    cpB(0, 0);
    CP_COMMIT();

    // ---- mainloop ----
    for (int t = 0; t < NT; t++) {
        const int st = t & 1;
        if (!ABF16) stsA(st);                 // A(t) regs -> smem
        if (t + 1 < NT) {
            const int sn = (t + 1) & 1;
            if (ABF16) cpA(t + 1, sn); else ldA(t + 1);
            cpB(t + 1, sn);
        }
        CP_COMMIT();
        if (t + 1 < NT) { CP_WAIT(1); } else { CP_WAIT(0); }
        __syncthreads();
        MMA(st);
        __syncthreads();
    }

    // ---- epilogue ----
    const int rBase = rowBase + warpM + (lid >> 2);
    const int cOff  = warpN + (lid & 3) * 2;
    #pragma unroll
    for (int i = 0; i < 2; i++) {
        #pragma unroll
        for (int j = 0; j < NJ; j++) {
            int cl = cOff + j * 8;
            int gc = colBase + cl;
            if (gc >= Mcols) continue;
            float2 bb = *(const float2*)(sm + OFF_BS + cl * 4);
            int r0 = rBase + i * 16;
            int r1 = r0 + 8;
            float2 v0, v1;
            v0.x = acc[i][j][0] + bb.x; v0.y = acc[i][j][1] + bb.y;
            v1.x = acc[i][j][2] + bb.x; v1.y = acc[i][j][3] + bb.y;
            if (RELU) {
                v0.x = fmaxf(v0.x, 0.f); v0.y = fmaxf(v0.y, 0.f);
                v1.x = fmaxf(v1.x, 0.f); v1.y = fmaxf(v1.y, 0.f);
            }
            if (OUTSPLIT) {
                uint32_t h0, l0, h1v, l1;
                split2(v0, h0, l0);
                split2(v1, h1v, l1);
                if (r0 < Nrows) {
                    *(uint32_t*)(Chi + (size_t)r0 * Mcols + gc) = h0;
                    *(uint32_t*)(Clo + (size_t)r0 * Mcols + gc) = l0;
                }
                if (r1 < Nrows) {
                    *(uint32_t*)(Chi + (size_t)r1 * Mcols + gc) = h1v;
                    *(uint32_t*)(Clo + (size_t)r1 * Mcols + gc) = l1;
                }
            } else {
                if (r0 < Nrows) *(float2*)(C + (size_t)r0 * Mcols + gc) = v0;
                if (r1 < Nrows) *(float2*)(C + (size_t)r1 * Mcols + gc) = v1;
            }
        }
    }
}

// ---------------- SpMM power-iteration step (smem-staged indices) ----------------
// Block = 320 threads = 32 rows x 10 f-groups. Edge indices for the block's 32
// contiguous CSR rows are staged once into smem (vs 10x redundant global reads).
#define SP_ROWS   32
#define SP_THREADS 320
#define SP_MAXE   6144     // 24KB; mean block edges ~512, fallback if exceeded

__global__ __launch_bounds__(SP_THREADS)
void spmm_step(const float4* __restrict__ v4, const float4* __restrict__ h4,
               float4* __restrict__ out4)
{
    __shared__ int sidx[SP_MAXE];

    const int tid = threadIdx.x;
    const int r0  = blockIdx.x * SP_ROWS;
    const int s0  = g_rowstart[r0];
    const int e0  = g_rowstart[r0 + SP_ROWS];   // N_NODES % 32 == 0
    const int ne  = e0 - s0;
    const bool use_sm = (ne <= SP_MAXE);

    if (use_sm) {
        for (int i = tid; i < ne; i += SP_THREADS) sidx[i] = g_cols[s0 + i];
    }
    __syncthreads();

    const int r = r0 + tid / NF4;
    const int f = tid % NF4;

    const int s = g_rowstart[r];
    const int e = g_rowstart[r + 1];

    float ax = 0.f, ay = 0.f, az = 0.f, aw = 0.f;
    if (use_sm) {
        const int ls = s - s0, le = e - s0;
        int i = ls;
        for (; i + 4 <= le; i += 4) {
            int c0 = sidx[i + 0], c1 = sidx[i + 1];
            int c2 = sidx[i + 2], c3 = sidx[i + 3];
            float4 p0 = __ldg(v4 + (size_t)c0 * NF4 + f);
            float4 p1 = __ldg(v4 + (size_t)c1 * NF4 + f);
            float4 p2 = __ldg(v4 + (size_t)c2 * NF4 + f);
            float4 p3 = __ldg(v4 + (size_t)c3 * NF4 + f);
            ax += (p0.x + p1.x) + (p2.x + p3.x);
            ay += (p0.y + p1.y) + (p2.y + p3.y);
            az += (p0.z + p1.z) + (p2.z + p3.z);
            aw += (p0.w + p1.w) + (p2.w + p3.w);
        }
        for (; i < le; i++) {
            int c = sidx[i];
            float4 p = __ldg(v4 + (size_t)c * NF4 + f);
            ax += p.x; ay += p.y; az += p.z; aw += p.w;
        }
    } else {
        int i = s;
        for (; i + 4 <= e; i += 4) {
            int c0 = g_cols[i + 0], c1 = g_cols[i + 1];
            int c2 = g_cols[i + 2], c3 = g_cols[i + 3];
            float4 p0 = __ldg(v4 + (size_t)c0 * NF4 + f);
            float4 p1 = __ldg(v4 + (size_t)c1 * NF4 + f);
            float4 p2 = __ldg(v4 + (size_t)c2 * NF4 + f);
            float4 p3 = __ldg(v4 + (size_t)c3 * NF4 + f);
            ax += (p0.x + p1.x) + (p2.x + p3.x);
            ay += (p0.y + p1.y) + (p2.y + p3.y);
            az += (p0.z + p1.z) + (p2.z + p3.z);
            aw += (p0.w + p1.w) + (p2.w + p3.w);
        }
        for (; i < e; i++) {
            int c = g_cols[i];
            float4 p = __ldg(v4 + (size_t)c * NF4 + f);
            ax += p.x; ay += p.y; az += p.z; aw += p.w;
        }
    }

    float4 vr = __ldg(v4 + (size_t)r * NF4 + f);
    float4 hr = __ldg(h4 + (size_t)r * NF4 + f);
    float  w  = 0.5f * g_dinv[r];

    float4 o;
    o.x = w * (ax + vr.x) + 0.5f * hr.x;
    o.y = w * (ay + vr.y) + 0.5f * hr.y;
    o.z = w * (az + vr.z) + 0.5f * hr.z;
    o.w = w * (aw + vr.w) + 0.5f * hr.w;
    out4[(size_t)r * NF4 + f] = o;
}

// ---------------- host ----------------
extern "C" void kernel_launch(void* const* d_in, const int* in_sizes, int n_in,
                              void* d_out, int out_size)
{
    const float* x  = (const float*)d_in[0];
    const int*   ei = (const int*)  d_in[1];
    const float* W1 = (const float*)d_in[2];
    const float* b1 = (const float*)d_in[3];
    const float* W2 = (const float*)d_in[4];
    const float* b2 = (const float*)d_in[5];
    const float* W3 = (const float*)d_in[6];
    const float* b3 = (const float*)d_in[7];
    float* out = (float*)d_out;

    const int* rows = ei;
    const int* cols = ei + N_EDGES;

    void *p;
    float *h1, *h2, *h, *vA, *vB;
    __nv_bfloat16 *w1hi, *w1lo, *w2hi, *w2lo, *w3hi, *w3lo;
    cudaGetSymbolAddress(&p, g_h1);   h1 = (float*)p;
    cudaGetSymbolAddress(&p, g_h2);   h2 = (float*)p;
    cudaGetSymbolAddress(&p, g_h);    h  = (float*)p;
    cudaGetSymbolAddress(&p, g_vA);   vA = (float*)p;
    cudaGetSymbolAddress(&p, g_vB);   vB = (float*)p;
    cudaGetSymbolAddress(&p, g_w1hi); w1hi = (__nv_bfloat16*)p;
    cudaGetSymbolAddress(&p, g_w1lo); w1lo = (__nv_bfloat16*)p;
    cudaGetSymbolAddress(&p, g_w2hi); w2hi = (__nv_bfloat16*)p;
    cudaGetSymbolAddress(&p, g_w2lo); w2lo = (__nv_bfloat16*)p;
    cudaGetSymbolAddress(&p, g_w3hi); w3hi = (__nv_bfloat16*)p;
    cudaGetSymbolAddress(&p, g_w3lo); w3lo = (__nv_bfloat16*)p;

    __nv_bfloat16* h1hi = (__nv_bfloat16*)h1;
    __nv_bfloat16* h1lo = h1hi + (size_t)N_NODES * NHID;
    __nv_bfloat16* h2hi = (__nv_bfloat16*)h2;
    __nv_bfloat16* h2lo = h2hi + (size_t)N_NODES * NHID;

    // side stream + events for CSR overlap
    cudaStream_t s1;
    cudaStreamCreateWithFlags(&s1, cudaStreamNonBlocking);
    cudaEvent_t evFork, evJoin;
    cudaEventCreateWithFlags(&evFork, cudaEventDisableTiming);
    cudaEventCreateWithFlags(&evJoin, cudaEventDisableTiming);

    // ---- fork: CSR build on side stream, concurrent with GEMM chain ----
    cudaEventRecord(evFork, 0);
    cudaStreamWaitEvent(s1, evFork, 0);
    zero_counts  <<<(N_NODES + 255) / 256, 256, 0, s1>>>();
    count_deg    <<<(N_EDGES + 255) / 256, 256, 0, s1>>>(rows);
    compute_dinv <<<(N_NODES + 255) / 256, 256, 0, s1>>>();
    scan_blocks  <<<NBLK, SCAN_T, 0, s1>>>();
    scan_offsets <<<1, 32, 0, s1>>>();
    scan_add     <<<NBLK, SCAN_T, 0, s1>>>();
    scatter_edges<<<(N_EDGES + 255) / 256, 256, 0, s1>>>(rows, cols);
    cudaEventRecord(evJoin, s1);

    // ---- main stream: weight splits (tiny) + GEMM chain ----
    split_w<<<(NHID * NFEAT  + 255) / 256, 256>>>(W1, w1hi, w1lo, NHID * NFEAT);
    split_w<<<(NHID * NHID   + 255) / 256, 256>>>(W2, w2hi, w2lo, NHID * NHID);
    split_w<<<(NCLASS * NHID + 255) / 256, 256>>>(W3, w3hi, w3lo, NCLASS * NHID);

    const int STG128 = 2 * (128 * RSB) + 2 * (128 * RSB);   // 40960
    const int STG64  = 2 * (128 * RSB) + 2 * (64 * RSB);    // 30720
    const int SMEM_128 = 2 * STG128 + 128 * 4;              // 82432
    const int SMEM_64  = 2 * STG64 + 64 * 4;                // 61696
    cudaFuncSetAttribute((const void*)gemm_hmma<128, 1, 0, 1>,
                         cudaFuncAttributeMaxDynamicSharedMemorySize, SMEM_128);
    cudaFuncSetAttribute((const void*)gemm_hmma<128, 1, 1, 1>,
                         cudaFuncAttributeMaxDynamicSharedMemorySize, SMEM_128);
    cudaFuncSetAttribute((const void*)gemm_hmma<64, 0, 1, 0>,
                         cudaFuncAttributeMaxDynamicSharedMemorySize, SMEM_64);

    const int MG = (N_NODES + 127) / 128;   // 782
    gemm_hmma<128, 1, 0, 1><<<dim3(2, MG), 256, SMEM_128>>>(
        x, nullptr, nullptr, w1hi, w1lo, b1, nullptr, h1hi, h1lo, N_NODES, NHID, NFEAT);
    gemm_hmma<128, 1, 1, 1><<<dim3(2, MG), 256, SMEM_128>>>(
        nullptr, h1hi, h1lo, w2hi, w2lo, b2, nullptr, h2hi, h2lo, N_NODES, NHID, NHID);
    gemm_hmma<64, 0, 1, 0><<<dim3(1, MG), 256, SMEM_64>>>(
        nullptr, h2hi, h2lo, w3hi, w3lo, b3, h, nullptr, nullptr, N_NODES, NCLASS, NHID);

    // ---- join: CSR must be done before propagation ----
    cudaStreamWaitEvent(0, evJoin, 0);

    // ---- 10 power iterations ----
    const int SP_G = N_NODES / SP_ROWS;   // 3125
    const float* src = h;
    for (int it = 0; it < 10; it++) {
        float* dst = (it == 9) ? out : ((it & 1) ? vB : vA);
        spmm_step<<<SP_G, SP_THREADS>>>((const float4*)src, (const float4*)h, (float4*)dst);
        src = dst;
    }
}

// round 12
// speedup vs baseline: 1.0938x; 1.0938x over previous
#include <cuda_runtime.h>
#include <cuda_bf16.h>
#include <cuda_fp16.h>
#include <cstdint>

#define N_NODES 100000
#define N_EDGES 1600000
#define NFEAT   512
#define NHID    256
#define NCLASS  40
#define NF4     (NCLASS / 4)

#define SCAN_T  1024
#define NBLK    ((N_NODES + SCAN_T - 1) / SCAN_T)   // 98

// ---------------- scratch (static device globals; no allocation) ----------------
__device__ float g_h1[(size_t)N_NODES * NHID];   // holds bf16 hi|lo of h1 (aliased)
__device__ float g_h2[(size_t)N_NODES * NHID];   // holds bf16 hi|lo of h2 (aliased)
__device__ float g_h [(size_t)N_NODES * NCLASS];
__device__ __align__(16) float g_vA[(size_t)N_NODES * NCLASS];  // fp16 iterate ping (aliased)
__device__ __align__(16) float g_vB[(size_t)N_NODES * NCLASS];  // fp16 iterate pong (aliased)
__device__ float g_dinv[N_NODES];
__device__ int   g_cnt [N_NODES];
__device__ int   g_fill[N_NODES];
__device__ int   g_rowstart[N_NODES + 1];
__device__ int   g_cols[N_EDGES];
__device__ int   g_bsum[128];
// pre-split weights (bf16 hi/lo), 16B-aligned
__device__ __align__(16) __nv_bfloat16 g_w1hi[NHID * NFEAT];
__device__ __align__(16) __nv_bfloat16 g_w1lo[NHID * NFEAT];
__device__ __align__(16) __nv_bfloat16 g_w2hi[NHID * NHID];
__device__ __align__(16) __nv_bfloat16 g_w2lo[NHID * NHID];
__device__ __align__(16) __nv_bfloat16 g_w3hi[NCLASS * NHID];
__device__ __align__(16) __nv_bfloat16 g_w3lo[NCLASS * NHID];

// ---------------- helpers ----------------
__device__ __forceinline__ uint32_t smem_u32(const void* p) {
    uint32_t a;
    asm("{ .reg .u64 t; cvta.to.shared.u64 t, %1; cvt.u32.u64 %0, t; }" : "=r"(a) : "l"(p));
    return a;
}

__device__ __forceinline__ void mma16816(float c[4], const uint32_t a[4],
                                         uint32_t b0, uint32_t b1) {
    asm volatile(
        "mma.sync.aligned.m16n8k16.row.col.f32.bf16.bf16.f32 "
        "{%0,%1,%2,%3}, {%4,%5,%6,%7}, {%8,%9}, {%0,%1,%2,%3};"
        : "+f"(c[0]), "+f"(c[1]), "+f"(c[2]), "+f"(c[3])
        : "r"(a[0]), "r"(a[1]), "r"(a[2]), "r"(a[3]), "r"(b0), "r"(b1));
}

#define LDSM_X4(r0, r1, r2, r3, addr) \
    asm volatile("ldmatrix.sync.aligned.m8n8.x4.shared.b16 {%0,%1,%2,%3}, [%4];" \
                 : "=r"(r0), "=r"(r1), "=r"(r2), "=r"(r3) : "r"(addr))

__device__ __forceinline__ void cp16(uint32_t dst, const void* src, uint32_t bytes) {
    asm volatile("cp.async.cg.shared.global [%0], [%1], 16, %2;"
                 :: "r"(dst), "l"(src), "r"(bytes));
}
#define CP_COMMIT() asm volatile("cp.async.commit_group;" ::: "memory")
#define CP_WAIT(n)  asm volatile("cp.async.wait_group %0;" :: "n"(n) : "memory")

__device__ __forceinline__ void split4(float4 v, uint2& hi, uint2& lo) {
    __nv_bfloat16 hx = __float2bfloat16(v.x);
    __nv_bfloat16 hy = __float2bfloat16(v.y);
    __nv_bfloat16 hz = __float2bfloat16(v.z);
    __nv_bfloat16 hw = __float2bfloat16(v.w);
    __nv_bfloat16 lx = __float2bfloat16(v.x - __bfloat162float(hx));
    __nv_bfloat16 ly = __float2bfloat16(v.y - __bfloat162float(hy));
    __nv_bfloat16 lz = __float2bfloat16(v.z - __bfloat162float(hz));
    __nv_bfloat16 lw = __float2bfloat16(v.w - __bfloat162float(hw));
    hi.x = ((uint32_t)__bfloat16_as_ushort(hy) << 16) | __bfloat16_as_ushort(hx);
    hi.y = ((uint32_t)__bfloat16_as_ushort(hw) << 16) | __bfloat16_as_ushort(hz);
    lo.x = ((uint32_t)__bfloat16_as_ushort(ly) << 16) | __bfloat16_as_ushort(lx);
    lo.y = ((uint32_t)__bfloat16_as_ushort(lw) << 16) | __bfloat16_as_ushort(lz);
}

__device__ __forceinline__ void split2(float2 v, uint32_t& hi, uint32_t& lo) {
    __nv_bfloat16 hx = __float2bfloat16(v.x);
    __nv_bfloat16 hy = __float2bfloat16(v.y);
    __nv_bfloat16 lx = __float2bfloat16(v.x - __bfloat162float(hx));
    __nv_bfloat16 ly = __float2bfloat16(v.y - __bfloat162float(hy));
    hi = ((uint32_t)__bfloat16_as_ushort(hy) << 16) | __bfloat16_as_ushort(hx);
    lo = ((uint32_t)__bfloat16_as_ushort(ly) << 16) | __bfloat16_as_ushort(lx);
}

// unpack a uint4 (8 fp16) and accumulate into 8 floats
__device__ __forceinline__ void acc8(float a[8], uint4 p) {
    float2 q;
    q = __half22float2(*(__half2*)&p.x); a[0] += q.x; a[1] += q.y;
    q = __half22float2(*(__half2*)&p.y); a[2] += q.x; a[3] += q.y;
    q = __half22float2(*(__half2*)&p.z); a[4] += q.x; a[5] += q.y;
    q = __half22float2(*(__half2*)&p.w); a[6] += q.x; a[7] += q.y;
}

// ---------------- graph preprocessing ----------------
__global__ void zero_counts() {
    int i = blockIdx.x * blockDim.x + threadIdx.x;
    if (i < N_NODES) { g_cnt[i] = 0; g_fill[i] = 0; }
}
__global__ void count_deg(const int* __restrict__ rows) {
    int e = blockIdx.x * blockDim.x + threadIdx.x;
    if (e < N_EDGES) atomicAdd(&g_cnt[rows[e]], 1);
}
__global__ void compute_dinv() {
    int i = blockIdx.x * blockDim.x + threadIdx.x;
    if (i < N_NODES) g_dinv[i] = 1.0f / (float)(g_cnt[i] + 1);
}
__global__ void scan_blocks() {
    __shared__ int s[SCAN_T];
    int t   = threadIdx.x;
    int gid = blockIdx.x * SCAN_T + t;
    int v   = (gid < N_NODES) ? g_cnt[gid] : 0;
    s[t] = v;
    __syncthreads();
    #pragma unroll
    for (int off = 1; off < SCAN_T; off <<= 1) {
        int x = (t >= off) ? s[t - off] : 0;
        __syncthreads();
        s[t] += x;
        __syncthreads();
    }
    if (gid < N_NODES) g_rowstart[gid] = s[t] - v;
    if (t == SCAN_T - 1) g_bsum[blockIdx.x] = s[t];
}
__global__ void scan_offsets() {
    if (threadIdx.x == 0 && blockIdx.x == 0) {
        int acc = 0;
        for (int i = 0; i < NBLK; i++) { int t = g_bsum[i]; g_bsum[i] = acc; acc += t; }
        g_rowstart[N_NODES] = acc;
    }
}
__global__ void scan_add() {
    int t   = threadIdx.x;
    int gid = blockIdx.x * SCAN_T + t;
    if (gid < N_NODES) g_rowstart[gid] += g_bsum[blockIdx.x];
}
__global__ void scatter_edges(const int* __restrict__ rows, const int* __restrict__ cols) {
    int e = blockIdx.x * blockDim.x + threadIdx.x;
    if (e < N_EDGES) {
        int r   = rows[e];
        int pos = g_rowstart[r] + atomicAdd(&g_fill[r], 1);
        g_cols[pos] = cols[e];
    }
}
__global__ void split_w(const float* __restrict__ src, __nv_bfloat16* __restrict__ hi,
                        __nv_bfloat16* __restrict__ lo, int n) {
    int i = blockIdx.x * 256 + threadIdx.x;
    if (i < n) {
        float v = src[i];
        __nv_bfloat16 h = __float2bfloat16(v);
        hi[i] = h;
        lo[i] = __float2bfloat16(v - __bfloat162float(h));
    }
}
// h (fp32) -> fp16 iterate v0
__global__ void h_to_half(const float2* __restrict__ src, uint32_t* __restrict__ dst, int n2) {
    int i = blockIdx.x * 256 + threadIdx.x;
    if (i < n2) {
        float2 v = src[i];
        __half2 h = __floats2half2_rn(v.x, v.y);
        dst[i] = *(uint32_t*)&h;
    }
}

// ====== HMMA GEMM, bf16 3-term split, K-tile 32, 2-stage cp.async pipeline ======
#define RSB 80             // smem row stride bytes (64B data + 16B pad)

template<int BN, int RELU, int ABF16, int OUTSPLIT>
__global__ __launch_bounds__(256, 2)
void gemm_hmma(const float* __restrict__ Af,
               const __nv_bfloat16* __restrict__ Ahi_g,
               const __nv_bfloat16* __restrict__ Alo_g,
               const __nv_bfloat16* __restrict__ Whi_g,
               const __nv_bfloat16* __restrict__ Wlo_g,
               const float* __restrict__ bias,
               float* __restrict__ C,
               __nv_bfloat16* __restrict__ Chi,
               __nv_bfloat16* __restrict__ Clo,
               int Nrows, int Mcols, int K)
{
    constexpr int NJ      = BN / 16;
    constexpr int ABYTES  = 128 * RSB;                   // 10240
    constexpr int BBYTES  = BN * RSB;
    constexpr int STAGE   = 2 * ABYTES + 2 * BBYTES;     // AHI|ALO|BHI|BLO
    constexpr int OFF_BS  = 2 * STAGE;
    constexpr int BCHUNKS = BN / 64;                     // cp.async 16B iters for B

    extern __shared__ __align__(16) char sm[];

    const uint32_t smb = smem_u32(sm);
    const int tid = threadIdx.x;
    const int wid = tid >> 5;
    const int lid = tid & 31;
    const int warpM = (wid & 3) * 32;
    const int warpN = (wid >> 2) * (BN / 2);
    const int rowBase = blockIdx.y * 128;
    const int colBase = blockIdx.x * BN;
    const int NT = K / 32;

    // bias -> smem
    for (int i = tid; i < BN; i += 256) {
        int gc = colBase + i;
        *(float*)(sm + OFF_BS + i * 4) = (gc < Mcols) ? bias[gc] : 0.0f;
    }

    // per-lane ldmatrix address components
    const int aRow  = (lid & 7) + ((lid >> 3) & 1) * 8;
    const int aColB = (lid >> 4) * 16;
    const int bN    = ((lid >> 4) * 8) + (lid & 7);
    const int bColB = ((lid >> 3) & 1) * 16;

    const uint32_t aAddr0 = smb + (warpM + aRow) * RSB + aColB;
    const uint32_t bAddr0 = smb + 2 * ABYTES + (warpN + bN) * RSB + bColB;

    float acc[2][NJ][4];
    #pragma unroll
    for (int i = 0; i < 2; i++)
        #pragma unroll
        for (int j = 0; j < NJ; j++)
            #pragma unroll
            for (int q = 0; q < 4; q++) acc[i][j][q] = 0.0f;

    float4 paf[4];   // fp32-A prefetch (ABF16=0 only)

    auto cpA = [&](int t, int st) {
        const int kt = t * 32;
        char* base = sm + st * STAGE;
        #pragma unroll
        for (int i = 0; i < 2; i++) {
            int idx = tid + i * 256;
            int row = idx >> 2;
            int c   = idx & 3;
            int gr  = rowBase + row;
            uint32_t sz = (gr < Nrows) ? 16u : 0u;
            int gra = (gr < Nrows) ? gr : 0;
            uint32_t so = smem_u32(base + row * RSB + c * 16);
            cp16(so,          Ahi_g + (size_t)gra * K + kt + c * 8, sz);
            cp16(so + ABYTES, Alo_g + (size_t)gra * K + kt + c * 8, sz);
        }
    };
    auto cpB = [&](int t, int st) {
        const int kt = t * 32;
        char* base = sm + st * STAGE + 2 * ABYTES;
        #pragma unroll
        for (int i = 0; i < BCHUNKS; i++) {
            int idx = tid + i * 256;
            int row = idx >> 2;
            int c   = idx & 3;
            int gm  = colBase + row;
            uint32_t sz = (gm < Mcols) ? 16u : 0u;
            int gma = (gm < Mcols) ? gm : 0;
            uint32_t so = smem_u32(base + row * RSB + c * 16);
            cp16(so,          Whi_g + (size_t)gma * K + kt + c * 8, sz);
            cp16(so + BBYTES, Wlo_g + (size_t)gma * K + kt + c * 8, sz);
        }
    };
    auto ldA = [&](int t) {
        const int kt = t * 32;
        #pragma unroll
        for (int i = 0; i < 4; i++) {
            int idx = tid + i * 256;
            int row = idx >> 3;
            int c4  = idx & 7;
            int gr  = rowBase + row;
            paf[i] = make_float4(0.f, 0.f, 0.f, 0.f);
            if (gr < Nrows) paf[i] = *(const float4*)(Af + (size_t)gr * K + kt + c4 * 4);
        }
    };
    auto stsA = [&](int st) {
        char* base = sm + st * STAGE;
        #pragma unroll
        for (int i = 0; i < 4; i++) {
            int idx = tid + i * 256;
            int row = idx >> 3;
            int c4  = idx & 7;
            uint2 hi, lo; split4(paf[i], hi, lo);
            *(uint2*)(base + row * RSB + c4 * 8) = hi;
            *(uint2*)(base + ABYTES + row * RSB + c4 * 8) = lo;
        }
    };

    auto MMA = [&](int st) {
        const uint32_t aA = aAddr0 + st * STAGE;
        const uint32_t bA = bAddr0 + st * STAGE;
        #pragma unroll
        for (int ks = 0; ks < 2; ks++) {
            const uint32_t kOff = ks * 32;
            uint32_t ah[2][4], al[2][4];
            #pragma unroll
            for (int i = 0; i < 2; i++) {
                uint32_t aa = aA + i * 16 * RSB + kOff;
                LDSM_X4(ah[i][0], ah[i][1], ah[i][2], ah[i][3], aa);
                LDSM_X4(al[i][0], al[i][1], al[i][2], al[i][3], aa + ABYTES);
            }
            #pragma unroll
            for (int jp = 0; jp < NJ / 2; jp++) {
                uint32_t bb = bA + jp * 16 * RSB + kOff;
                uint32_t bh0, bh1, bh2, bh3, bl0, bl1, bl2, bl3;
                LDSM_X4(bh0, bh1, bh2, bh3, bb);
                LDSM_X4(bl0, bl1, bl2, bl3, bb + BBYTES);
                #pragma unroll
                for (int i = 0; i < 2; i++) {
                    mma16816(acc[i][2 * jp],     ah[i], bh0, bh1);
                    mma16816(acc[i][2 * jp],     ah[i], bl0, bl1);
                    mma16816(acc[i][2 * jp],     al[i], bh0, bh1);
                    mma16816(acc[i][2 * jp + 1], ah[i], bh2, bh3);
                    mma16816(acc[i][2 * jp + 1], ah[i], bl2, bl3);
                    mma16816(acc[i][2 * jp + 1], al[i], bh2, bh3);
                }
            }
        }
    };

    // ---- prologue ----
    if (ABF16) cpA(0, 0); else ldA(0);
    cpB(0, 0);
    CP_COMMIT();

    // ---- mainloop ----
    for (int t = 0; t < NT; t++) {
        const int st = t & 1;
        if (!ABF16) stsA(st);
        if (t + 1 < NT) {
            const int sn = (t + 1) & 1;
            if (ABF16) cpA(t + 1, sn); else ldA(t + 1);
            cpB(t + 1, sn);
        }
        CP_COMMIT();
        if (t + 1 < NT) { CP_WAIT(1); } else { CP_WAIT(0); }
        __syncthreads();
        MMA(st);
        __syncthreads();
    }

    // ---- epilogue ----
    const int rBase = rowBase + warpM + (lid >> 2);
    const int cOff  = warpN + (lid & 3) * 2;
    #pragma unroll
    for (int i = 0; i < 2; i++) {
        #pragma unroll
        for (int j = 0; j < NJ; j++) {
            int cl = cOff + j * 8;
            int gc = colBase + cl;
            if (gc >= Mcols) continue;
            float2 bb = *(const float2*)(sm + OFF_BS + cl * 4);
            int r0 = rBase + i * 16;
            int r1 = r0 + 8;
            float2 v0, v1;
            v0.x = acc[i][j][0] + bb.x; v0.y = acc[i][j][1] + bb.y;
            v1.x = acc[i][j][2] + bb.x; v1.y = acc[i][j][3] + bb.y;
            if (RELU) {
                v0.x = fmaxf(v0.x, 0.f); v0.y = fmaxf(v0.y, 0.f);
                v1.x = fmaxf(v1.x, 0.f); v1.y = fmaxf(v1.y, 0.f);
            }
            if (OUTSPLIT) {
                uint32_t h0, l0, h1v, l1;
                split2(v0, h0, l0);
                split2(v1, h1v, l1);
                if (r0 < Nrows) {
                    *(uint32_t*)(Chi + (size_t)r0 * Mcols + gc) = h0;
                    *(uint32_t*)(Clo + (size_t)r0 * Mcols + gc) = l0;
                }
                if (r1 < Nrows) {
                    *(uint32_t*)(Chi + (size_t)r1 * Mcols + gc) = h1v;
                    *(uint32_t*)(Clo + (size_t)r1 * Mcols + gc) = l1;
                }
            } else {
                if (r0 < Nrows) *(float2*)(C + (size_t)r0 * Mcols + gc) = v0;
                if (r1 < Nrows) *(float2*)(C + (size_t)r1 * Mcols + gc) = v1;
            }
        }
    }
}

// ---------------- SpMM power-iteration step, fp16 iterate ----------------
// 5 threads/row, each owns one uint4 (8 fp16 features). Accumulate fp32.
#define SPH_T 320

template<int FINAL>
__global__ __launch_bounds__(SPH_T)
void spmm_h(const uint4* __restrict__ vh,     // fp16 iterate: 5 uint4 per row
            const float4* __restrict__ hf,    // fp32 h: 10 float4 per row
            uint4* __restrict__ dsth,         // fp16 out (FINAL=0)
            float4* __restrict__ dstf)        // fp32 out (FINAL=1)
{
    int t = blockIdx.x * SPH_T + threadIdx.x;
    int r = t / 5;
    int f = t - r * 5;
    if (r >= N_NODES) return;

    const int s = g_rowstart[r];
    const int e = g_rowstart[r + 1];

    float a[8];
    #pragma unroll
    for (int j = 0; j < 8; j++) a[j] = 0.0f;

    int i = s;
    for (; i + 4 <= e; i += 4) {
        int c0 = g_cols[i + 0], c1 = g_cols[i + 1];
        int c2 = g_cols[i + 2], c3 = g_cols[i + 3];
        uint4 p0 = __ldg(vh + (size_t)c0 * 5 + f);
        uint4 p1 = __ldg(vh + (size_t)c1 * 5 + f);
        uint4 p2 = __ldg(vh + (size_t)c2 * 5 + f);
        uint4 p3 = __ldg(vh + (size_t)c3 * 5 + f);
        acc8(a, p0); acc8(a, p1); acc8(a, p2); acc8(a, p3);
    }
    for (; i < e; i++) {
        uint4 p = __ldg(vh + (size_t)g_cols[i] * 5 + f);
        acc8(a, p);
    }

    // self-loop term (fp16 iterate)
    {
        uint4 p = __ldg(vh + (size_t)r * 5 + f);
        acc8(a, p);
    }

    const float w = 0.5f * g_dinv[r];
    float4 h0 = __ldg(hf + (size_t)r * 10 + f * 2);
    float4 h1 = __ldg(hf + (size_t)r * 10 + f * 2 + 1);

    float o[8];
    o[0] = w * a[0] + 0.5f * h0.x;
    o[1] = w * a[1] + 0.5f * h0.y;
    o[2] = w * a[2] + 0.5f * h0.z;
    o[3] = w * a[3] + 0.5f * h0.w;
    o[4] = w * a[4] + 0.5f * h1.x;
    o[5] = w * a[5] + 0.5f * h1.y;
    o[6] = w * a[6] + 0.5f * h1.z;
    o[7] = w * a[7] + 0.5f * h1.w;

    if (FINAL) {
        dstf[(size_t)r * 10 + f * 2]     = make_float4(o[0], o[1], o[2], o[3]);
        dstf[(size_t)r * 10 + f * 2 + 1] = make_float4(o[4], o[5], o[6], o[7]);
    } else {
        __half2 q0 = __floats2half2_rn(o[0], o[1]);
        __half2 q1 = __floats2half2_rn(o[2], o[3]);
        __half2 q2 = __floats2half2_rn(o[4], o[5]);
        __half2 q3 = __floats2half2_rn(o[6], o[7]);
        uint4 pk;
        pk.x = *(uint32_t*)&q0; pk.y = *(uint32_t*)&q1;
        pk.z = *(uint32_t*)&q2; pk.w = *(uint32_t*)&q3;
        dsth[(size_t)r * 5 + f] = pk;
    }
}

// ---------------- host ----------------
extern "C" void kernel_launch(void* const* d_in, const int* in_sizes, int n_in,
                              void* d_out, int out_size)
{
    const float* x  = (const float*)d_in[0];
    const int*   ei = (const int*)  d_in[1];
    const float* W1 = (const float*)d_in[2];
    const float* b1 = (const float*)d_in[3];
    const float* W2 = (const float*)d_in[4];
    const float* b2 = (const float*)d_in[5];
    const float* W3 = (const float*)d_in[6];
    const float* b3 = (const float*)d_in[7];
    float* out = (float*)d_out;

    const int* rows = ei;
    const int* cols = ei + N_EDGES;

    void *p;
    float *h1, *h2, *h, *vA, *vB;
    __nv_bfloat16 *w1hi, *w1lo, *w2hi, *w2lo, *w3hi, *w3lo;
    cudaGetSymbolAddress(&p, g_h1);   h1 = (float*)p;
    cudaGetSymbolAddress(&p, g_h2);   h2 = (float*)p;
    cudaGetSymbolAddress(&p, g_h);    h  = (float*)p;
    cudaGetSymbolAddress(&p, g_vA);   vA = (float*)p;
    cudaGetSymbolAddress(&p, g_vB);   vB = (float*)p;
    cudaGetSymbolAddress(&p, g_w1hi); w1hi = (__nv_bfloat16*)p;
    cudaGetSymbolAddress(&p, g_w1lo); w1lo = (__nv_bfloat16*)p;
    cudaGetSymbolAddress(&p, g_w2hi); w2hi = (__nv_bfloat16*)p;
    cudaGetSymbolAddress(&p, g_w2lo); w2lo = (__nv_bfloat16*)p;
    cudaGetSymbolAddress(&p, g_w3hi); w3hi = (__nv_bfloat16*)p;
    cudaGetSymbolAddress(&p, g_w3lo); w3lo = (__nv_bfloat16*)p;

    __nv_bfloat16* h1hi = (__nv_bfloat16*)h1;
    __nv_bfloat16* h1lo = h1hi + (size_t)N_NODES * NHID;
    __nv_bfloat16* h2hi = (__nv_bfloat16*)h2;
    __nv_bfloat16* h2lo = h2hi + (size_t)N_NODES * NHID;

    // side stream + events for CSR overlap
    cudaStream_t s1;
    cudaStreamCreateWithFlags(&s1, cudaStreamNonBlocking);
    cudaEvent_t evFork, evJoin;
    cudaEventCreateWithFlags(&evFork, cudaEventDisableTiming);
    cudaEventCreateWithFlags(&evJoin, cudaEventDisableTiming);

    // ---- fork: CSR build on side stream, concurrent with GEMM chain ----
    cudaEventRecord(evFork, 0);
    cudaStreamWaitEvent(s1, evFork, 0);
    zero_counts  <<<(N_NODES + 255) / 256, 256, 0, s1>>>();
    count_deg    <<<(N_EDGES + 255) / 256, 256, 0, s1>>>(rows);
    compute_dinv <<<(N_NODES + 255) / 256, 256, 0, s1>>>();
    scan_blocks  <<<NBLK, SCAN_T, 0, s1>>>();
    scan_offsets <<<1, 32, 0, s1>>>();
    scan_add     <<<NBLK, SCAN_T, 0, s1>>>();
    scatter_edges<<<(N_EDGES + 255) / 256, 256, 0, s1>>>(rows, cols);
    cudaEventRecord(evJoin, s1);

    // ---- main stream: weight splits (tiny) + GEMM chain ----
    split_w<<<(NHID * NFEAT  + 255) / 256, 256>>>(W1, w1hi, w1lo, NHID * NFEAT);
    split_w<<<(NHID * NHID   + 255) / 256, 256>>>(W2, w2hi, w2lo, NHID * NHID);
    split_w<<<(NCLASS * NHID + 255) / 256, 256>>>(W3, w3hi, w3lo, NCLASS * NHID);

    const int STG128 = 2 * (128 * RSB) + 2 * (128 * RSB);   // 40960
    const int STG64  = 2 * (128 * RSB) + 2 * (64 * RSB);    // 30720
    const int SMEM_128 = 2 * STG128 + 128 * 4;              // 82432
    const int SMEM_64  = 2 * STG64 + 64 * 4;                // 61696
    cudaFuncSetAttribute((const void*)gemm_hmma<128, 1, 0, 1>,
                         cudaFuncAttributeMaxDynamicSharedMemorySize, SMEM_128);
    cudaFuncSetAttribute((const void*)gemm_hmma<128, 1, 1, 1>,
                         cudaFuncAttributeMaxDynamicSharedMemorySize, SMEM_128);
    cudaFuncSetAttribute((const void*)gemm_hmma<64, 0, 1, 0>,
                         cudaFuncAttributeMaxDynamicSharedMemorySize, SMEM_64);

    const int MG = (N_NODES + 127) / 128;   // 782
    gemm_hmma<128, 1, 0, 1><<<dim3(2, MG), 256, SMEM_128>>>(
        x, nullptr, nullptr, w1hi, w1lo, b1, nullptr, h1hi, h1lo, N_NODES, NHID, NFEAT);
    gemm_hmma<128, 1, 1, 1><<<dim3(2, MG), 256, SMEM_128>>>(
        nullptr, h1hi, h1lo, w2hi, w2lo, b2, nullptr, h2hi, h2lo, N_NODES, NHID, NHID);
    gemm_hmma<64, 0, 1, 0><<<dim3(1, MG), 256, SMEM_64>>>(
        nullptr, h2hi, h2lo, w3hi, w3lo, b3, h, nullptr, nullptr, N_NODES, NCLASS, NHID);

    // v0 = fp16(h)
    h_to_half<<<(N_NODES * (NCLASS / 2) + 255) / 256, 256>>>(
        (const float2*)h, (uint32_t*)vA, N_NODES * (NCLASS / 2));

    // ---- join: CSR must be done before propagation ----
    cudaStreamWaitEvent(0, evJoin, 0);

    // ---- 10 power iterations (fp16 iterate, fp32 h-term and final) ----
    const int SP_G = (N_NODES * 5 + SPH_T - 1) / SPH_T;   // 1563
    const uint4* src = (const uint4*)vA;
    for (int it = 0; it < 9; it++) {
        uint4* dst = (uint4*)((it & 1) ? vA : vB);
        spmm_h<0><<<SP_G, SPH_T>>>(src, (const float4*)h, dst, nullptr);
        src = dst;
    }
    spmm_h<1><<<SP_G, SPH_T>>>(src, (const float4*)h, nullptr, (float4*)out);
}

// round 13
// speedup vs baseline: 1.1056x; 1.0108x over previous
#include <cuda_runtime.h>
#include <cuda_bf16.h>
#include <cuda_fp16.h>
#include <cstdint>

#define N_NODES 100000
#define N_EDGES 1600000
#define NFEAT   512
#define NHID    256
#define NCLASS  40
#define NF4     (NCLASS / 4)

#define SCAN_T  1024
#define NBLK    ((N_NODES + SCAN_T - 1) / SCAN_T)   // 98

// ---------------- scratch (static device globals; no allocation) ----------------
__device__ float g_h1[(size_t)N_NODES * NHID];   // holds bf16 hi|lo of h1 (aliased)
__device__ float g_h2[(size_t)N_NODES * NHID];   // holds bf16 hi|lo of h2 (aliased)
__device__ float g_h [(size_t)N_NODES * NCLASS];
__device__ __align__(16) float g_vA[(size_t)N_NODES * NCLASS];  // fp16 iterate ping (aliased)
__device__ __align__(16) float g_vB[(size_t)N_NODES * NCLASS];  // fp16 iterate pong (aliased)
__device__ float g_dinv[N_NODES];
__device__ int   g_cnt [N_NODES];
__device__ int   g_fill[N_NODES];
__device__ int   g_rowstart[N_NODES + 1];
__device__ int   g_cols[N_EDGES];
__device__ int   g_bsum[128];
// pre-split weights (bf16 hi/lo), 16B-aligned
__device__ __align__(16) __nv_bfloat16 g_w1hi[NHID * NFEAT];
__device__ __align__(16) __nv_bfloat16 g_w1lo[NHID * NFEAT];
__device__ __align__(16) __nv_bfloat16 g_w2hi[NHID * NHID];
__device__ __align__(16) __nv_bfloat16 g_w2lo[NHID * NHID];
__device__ __align__(16) __nv_bfloat16 g_w3hi[NCLASS * NHID];
__device__ __align__(16) __nv_bfloat16 g_w3lo[NCLASS * NHID];

// ---------------- helpers ----------------
__device__ __forceinline__ uint32_t smem_u32(const void* p) {
    uint32_t a;
    asm("{ .reg .u64 t; cvta.to.shared.u64 t, %1; cvt.u32.u64 %0, t; }" : "=r"(a) : "l"(p));
    return a;
}

__device__ __forceinline__ void mma16816(float c[4], const uint32_t a[4],
                                         uint32_t b0, uint32_t b1) {
    asm volatile(
        "mma.sync.aligned.m16n8k16.row.col.f32.bf16.bf16.f32 "
        "{%0,%1,%2,%3}, {%4,%5,%6,%7}, {%8,%9}, {%0,%1,%2,%3};"
        : "+f"(c[0]), "+f"(c[1]), "+f"(c[2]), "+f"(c[3])
        : "r"(a[0]), "r"(a[1]), "r"(a[2]), "r"(a[3]), "r"(b0), "r"(b1));
}

#define LDSM_X4(r0, r1, r2, r3, addr) \
    asm volatile("ldmatrix.sync.aligned.m8n8.x4.shared.b16 {%0,%1,%2,%3}, [%4];" \
                 : "=r"(r0), "=r"(r1), "=r"(r2), "=r"(r3) : "r"(addr))

__device__ __forceinline__ void cp16(uint32_t dst, const void* src, uint32_t bytes) {
    asm volatile("cp.async.cg.shared.global [%0], [%1], 16, %2;"
                 :: "r"(dst), "l"(src), "r"(bytes));
}
#define CP_COMMIT() asm volatile("cp.async.commit_group;" ::: "memory")
#define CP_WAIT(n)  asm volatile("cp.async.wait_group %0;" :: "n"(n) : "memory")

__device__ __forceinline__ void split4(float4 v, uint2& hi, uint2& lo) {
    __nv_bfloat16 hx = __float2bfloat16(v.x);
    __nv_bfloat16 hy = __float2bfloat16(v.y);
    __nv_bfloat16 hz = __float2bfloat16(v.z);
    __nv_bfloat16 hw = __float2bfloat16(v.w);
    __nv_bfloat16 lx = __float2bfloat16(v.x - __bfloat162float(hx));
    __nv_bfloat16 ly = __float2bfloat16(v.y - __bfloat162float(hy));
    __nv_bfloat16 lz = __float2bfloat16(v.z - __bfloat162float(hz));
    __nv_bfloat16 lw = __float2bfloat16(v.w - __bfloat162float(hw));
    hi.x = ((uint32_t)__bfloat16_as_ushort(hy) << 16) | __bfloat16_as_ushort(hx);
    hi.y = ((uint32_t)__bfloat16_as_ushort(hw) << 16) | __bfloat16_as_ushort(hz);
    lo.x = ((uint32_t)__bfloat16_as_ushort(ly) << 16) | __bfloat16_as_ushort(lx);
    lo.y = ((uint32_t)__bfloat16_as_ushort(lw) << 16) | __bfloat16_as_ushort(lz);
}

__device__ __forceinline__ void split2(float2 v, uint32_t& hi, uint32_t& lo) {
    __nv_bfloat16 hx = __float2bfloat16(v.x);
    __nv_bfloat16 hy = __float2bfloat16(v.y);
    __nv_bfloat16 lx = __float2bfloat16(v.x - __bfloat162float(hx));
    __nv_bfloat16 ly = __float2bfloat16(v.y - __bfloat162float(hy));
    hi = ((uint32_t)__bfloat16_as_ushort(hy) << 16) | __bfloat16_as_ushort(hx);
    lo = ((uint32_t)__bfloat16_as_ushort(ly) << 16) | __bfloat16_as_ushort(lx);
}

// unpack a uint4 (8 fp16) and accumulate into 8 floats
__device__ __forceinline__ void acc8(float a[8], uint4 p) {
    float2 q;
    q = __half22float2(*(__half2*)&p.x); a[0] += q.x; a[1] += q.y;
    q = __half22float2(*(__half2*)&p.y); a[2] += q.x; a[3] += q.y;
    q = __half22float2(*(__half2*)&p.z); a[4] += q.x; a[5] += q.y;
    q = __half22float2(*(__half2*)&p.w); a[6] += q.x; a[7] += q.y;
}

// ---------------- graph preprocessing ----------------
__global__ void zero_counts() {
    int i = blockIdx.x * blockDim.x + threadIdx.x;
    if (i < N_NODES) { g_cnt[i] = 0; g_fill[i] = 0; }
}
__global__ void count_deg(const int* __restrict__ rows) {
    int e = blockIdx.x * blockDim.x + threadIdx.x;
    if (e < N_EDGES) atomicAdd(&g_cnt[rows[e]], 1);
}
__global__ void compute_dinv() {
    int i = blockIdx.x * blockDim.x + threadIdx.x;
    if (i < N_NODES) g_dinv[i] = 1.0f / (float)(g_cnt[i] + 1);
}
__global__ void scan_blocks() {
    __shared__ int s[SCAN_T];
    int t   = threadIdx.x;
    int gid = blockIdx.x * SCAN_T + t;
    int v   = (gid < N_NODES) ? g_cnt[gid] : 0;
    s[t] = v;
    __syncthreads();
    #pragma unroll
    for (int off = 1; off < SCAN_T; off <<= 1) {
        int x = (t >= off) ? s[t - off] : 0;
        __syncthreads();
        s[t] += x;
        __syncthreads();
    }
    if (gid < N_NODES) g_rowstart[gid] = s[t] - v;
    if (t == SCAN_T - 1) g_bsum[blockIdx.x] = s[t];
}
__global__ void scan_offsets() {
    if (threadIdx.x == 0 && blockIdx.x == 0) {
        int acc = 0;
        for (int i = 0; i < NBLK; i++) { int t = g_bsum[i]; g_bsum[i] = acc; acc += t; }
        g_rowstart[N_NODES] = acc;
    }
}
__global__ void scan_add() {
    int t   = threadIdx.x;
    int gid = blockIdx.x * SCAN_T + t;
    if (gid < N_NODES) g_rowstart[gid] += g_bsum[blockIdx.x];
}
__global__ void scatter_edges(const int* __restrict__ rows, const int* __restrict__ cols) {
    int e = blockIdx.x * blockDim.x + threadIdx.x;
    if (e < N_EDGES) {
        int r   = rows[e];
        int pos = g_rowstart[r] + atomicAdd(&g_fill[r], 1);
        g_cols[pos] = cols[e];
    }
}
__global__ void split_w(const float* __restrict__ src, __nv_bfloat16* __restrict__ hi,
                        __nv_bfloat16* __restrict__ lo, int n) {
    int i = blockIdx.x * 256 + threadIdx.x;
    if (i < n) {
        float v = src[i];
        __nv_bfloat16 h = __float2bfloat16(v);
        hi[i] = h;
        lo[i] = __float2bfloat16(v - __bfloat162float(h));
    }
}

// ====== HMMA GEMM, bf16 3-term split, K-tile 32, 2-stage cp.async pipeline ======
// OUTMODE: 0 = fp32 C only; 1 = bf16 hi/lo (next GEMM layer); 2 = fp32 C + fp16 v0
#define RSB 80             // smem row stride bytes (64B data + 16B pad)

template<int BN, int RELU, int ABF16, int OUTMODE>
__global__ __launch_bounds__(256, 2)
void gemm_hmma(const float* __restrict__ Af,
               const __nv_bfloat16* __restrict__ Ahi_g,
               const __nv_bfloat16* __restrict__ Alo_g,
               const __nv_bfloat16* __restrict__ Whi_g,
               const __nv_bfloat16* __restrict__ Wlo_g,
               const float* __restrict__ bias,
               float* __restrict__ C,
               __nv_bfloat16* __restrict__ Chi,
               __nv_bfloat16* __restrict__ Clo,
               __half* __restrict__ Chalf,
               int Nrows, int Mcols, int K)
{
    constexpr int NJ      = BN / 16;
    constexpr int ABYTES  = 128 * RSB;                   // 10240
    constexpr int BBYTES  = BN * RSB;
    constexpr int STAGE   = 2 * ABYTES + 2 * BBYTES;     // AHI|ALO|BHI|BLO
    constexpr int OFF_BS  = 2 * STAGE;
    constexpr int BCHUNKS = BN / 64;                     // cp.async 16B iters for B

    extern __shared__ __align__(16) char sm[];

    const uint32_t smb = smem_u32(sm);
    const int tid = threadIdx.x;
    const int wid = tid >> 5;
    const int lid = tid & 31;
    const int warpM = (wid & 3) * 32;
    const int warpN = (wid >> 2) * (BN / 2);
    const int rowBase = blockIdx.y * 128;
    const int colBase = blockIdx.x * BN;
    const int NT = K / 32;

    // bias -> smem
    for (int i = tid; i < BN; i += 256) {
        int gc = colBase + i;
        *(float*)(sm + OFF_BS + i * 4) = (gc < Mcols) ? bias[gc] : 0.0f;
    }

    // per-lane ldmatrix address components
    const int aRow  = (lid & 7) + ((lid >> 3) & 1) * 8;
    const int aColB = (lid >> 4) * 16;
    const int bN    = ((lid >> 4) * 8) + (lid & 7);
    const int bColB = ((lid >> 3) & 1) * 16;

    const uint32_t aAddr0 = smb + (warpM + aRow) * RSB + aColB;
    const uint32_t bAddr0 = smb + 2 * ABYTES + (warpN + bN) * RSB + bColB;

    float acc[2][NJ][4];
    #pragma unroll
    for (int i = 0; i < 2; i++)
        #pragma unroll
        for (int j = 0; j < NJ; j++)
            #pragma unroll
            for (int q = 0; q < 4; q++) acc[i][j][q] = 0.0f;

    float4 paf[4];   // fp32-A prefetch (ABF16=0 only)

    auto cpA = [&](int t, int st) {
        const int kt = t * 32;
        char* base = sm + st * STAGE;
        #pragma unroll
        for (int i = 0; i < 2; i++) {
            int idx = tid + i * 256;
            int row = idx >> 2;
            int c   = idx & 3;
            int gr  = rowBase + row;
            uint32_t sz = (gr < Nrows) ? 16u : 0u;
            int gra = (gr < Nrows) ? gr : 0;
            uint32_t so = smem_u32(base + row * RSB + c * 16);
            cp16(so,          Ahi_g + (size_t)gra * K + kt + c * 8, sz);
            cp16(so + ABYTES, Alo_g + (size_t)gra * K + kt + c * 8, sz);
        }
    };
    auto cpB = [&](int t, int st) {
        const int kt = t * 32;
        char* base = sm + st * STAGE + 2 * ABYTES;
        #pragma unroll
        for (int i = 0; i < BCHUNKS; i++) {
            int idx = tid + i * 256;
            int row = idx >> 2;
            int c   = idx & 3;
            int gm  = colBase + row;
            uint32_t sz = (gm < Mcols) ? 16u : 0u;
            int gma = (gm < Mcols) ? gm : 0;
            uint32_t so = smem_u32(base + row * RSB + c * 16);
            cp16(so,          Whi_g + (size_t)gma * K + kt + c * 8, sz);
            cp16(so + BBYTES, Wlo_g + (size_t)gma * K + kt + c * 8, sz);
        }
    };
    auto ldA = [&](int t) {
        const int kt = t * 32;
        #pragma unroll
        for (int i = 0; i < 4; i++) {
            int idx = tid + i * 256;
            int row = idx >> 3;
            int c4  = idx & 7;
            int gr  = rowBase + row;
            paf[i] = make_float4(0.f, 0.f, 0.f, 0.f);
            if (gr < Nrows) paf[i] = *(const float4*)(Af + (size_t)gr * K + kt + c4 * 4);
        }
    };
    auto stsA = [&](int st) {
        char* base = sm + st * STAGE;
        #pragma unroll
        for (int i = 0; i < 4; i++) {
            int idx = tid + i * 256;
            int row = idx >> 3;
            int c4  = idx & 7;
            uint2 hi, lo; split4(paf[i], hi, lo);
            *(uint2*)(base + row * RSB + c4 * 8) = hi;
            *(uint2*)(base + ABYTES + row * RSB + c4 * 8) = lo;
        }
    };

    auto MMA = [&](int st) {
        const uint32_t aA = aAddr0 + st * STAGE;
        const uint32_t bA = bAddr0 + st * STAGE;
        #pragma unroll
        for (int ks = 0; ks < 2; ks++) {
            const uint32_t kOff = ks * 32;
            uint32_t ah[2][4], al[2][4];
            #pragma unroll
            for (int i = 0; i < 2; i++) {
                uint32_t aa = aA + i * 16 * RSB + kOff;
                LDSM_X4(ah[i][0], ah[i][1], ah[i][2], ah[i][3], aa);
                LDSM_X4(al[i][0], al[i][1], al[i][2], al[i][3], aa + ABYTES);
            }
            #pragma unroll
            for (int jp = 0; jp < NJ / 2; jp++) {
                uint32_t bb = bA + jp * 16 * RSB + kOff;
                uint32_t bh0, bh1, bh2, bh3, bl0, bl1, bl2, bl3;
                LDSM_X4(bh0, bh1, bh2, bh3, bb);
                LDSM_X4(bl0, bl1, bl2, bl3, bb + BBYTES);
                #pragma unroll
                for (int i = 0; i < 2; i++) {
                    mma16816(acc[i][2 * jp],     ah[i], bh0, bh1);
                    mma16816(acc[i][2 * jp],     ah[i], bl0, bl1);
                    mma16816(acc[i][2 * jp],     al[i], bh0, bh1);
                    mma16816(acc[i][2 * jp + 1], ah[i], bh2, bh3);
                    mma16816(acc[i][2 * jp + 1], ah[i], bl2, bl3);
                    mma16816(acc[i][2 * jp + 1], al[i], bh2, bh3);
                }
            }
        }
    };

    // ---- prologue ----
    if (ABF16) cpA(0, 0); else ldA(0);
    cpB(0, 0);
    CP_COMMIT();

    // ---- mainloop ----
    for (int t = 0; t < NT; t++) {
        const int st = t & 1;
        if (!ABF16) stsA(st);
        if (t + 1 < NT) {
            const int sn = (t + 1) & 1;
            if (ABF16) cpA(t + 1, sn); else ldA(t + 1);
            cpB(t + 1, sn);
        }
        CP_COMMIT();
        if (t + 1 < NT) { CP_WAIT(1); } else { CP_WAIT(0); }
        __syncthreads();
        MMA(st);
        __syncthreads();
    }

    // ---- epilogue ----
    const int rBase = rowBase + warpM + (lid >> 2);
    const int cOff  = warpN + (lid & 3) * 2;
    #pragma unroll
    for (int i = 0; i < 2; i++) {
        #pragma unroll
        for (int j = 0; j < NJ; j++) {
            int cl = cOff + j * 8;
            int gc = colBase + cl;
            if (gc >= Mcols) continue;
            float2 bb = *(const float2*)(sm + OFF_BS + cl * 4);
            int r0 = rBase + i * 16;
            int r1 = r0 + 8;
            float2 v0, v1;
            v0.x = acc[i][j][0] + bb.x; v0.y = acc[i][j][1] + bb.y;
            v1.x = acc[i][j][2] + bb.x; v1.y = acc[i][j][3] + bb.y;
            if (RELU) {
                v0.x = fmaxf(v0.x, 0.f); v0.y = fmaxf(v0.y, 0.f);
                v1.x = fmaxf(v1.x, 0.f); v1.y = fmaxf(v1.y, 0.f);
            }
            if (OUTMODE == 1) {
                uint32_t h0, l0, h1v, l1;
                split2(v0, h0, l0);
                split2(v1, h1v, l1);
                if (r0 < Nrows) {
                    *(uint32_t*)(Chi + (size_t)r0 * Mcols + gc) = h0;
                    *(uint32_t*)(Clo + (size_t)r0 * Mcols + gc) = l0;
                }
                if (r1 < Nrows) {
                    *(uint32_t*)(Chi + (size_t)r1 * Mcols + gc) = h1v;
                    *(uint32_t*)(Clo + (size_t)r1 * Mcols + gc) = l1;
                }
            } else {
                if (r0 < Nrows) *(float2*)(C + (size_t)r0 * Mcols + gc) = v0;
                if (r1 < Nrows) *(float2*)(C + (size_t)r1 * Mcols + gc) = v1;
                if (OUTMODE == 2) {
                    // also emit fp16 v0 (gc is even -> 4B-aligned half2 store)
                    __half2 q0 = __floats2half2_rn(v0.x, v0.y);
                    __half2 q1 = __floats2half2_rn(v1.x, v1.y);
                    if (r0 < Nrows) *(uint32_t*)(Chalf + (size_t)r0 * Mcols + gc) = *(uint32_t*)&q0;
                    if (r1 < Nrows) *(uint32_t*)(Chalf + (size_t)r1 * Mcols + gc) = *(uint32_t*)&q1;
                }
            }
        }
    }
}

// ---------------- SpMM power-iteration step, fp16 iterate ----------------
#define SPH_T 320

template<int FINAL>
__global__ __launch_bounds__(SPH_T)
void spmm_h(const uint4* __restrict__ vh,     // fp16 iterate: 5 uint4 per row
            const float4* __restrict__ hf,    // fp32 h: 10 float4 per row
            uint4* __restrict__ dsth,         // fp16 out (FINAL=0)
            float4* __restrict__ dstf)        // fp32 out (FINAL=1)
{
    int t = blockIdx.x * SPH_T + threadIdx.x;
    int r = t / 5;
    int f = t - r * 5;
    if (r >= N_NODES) return;

    const int s = g_rowstart[r];
    const int e = g_rowstart[r + 1];

    float a[8];
    #pragma unroll
    for (int j = 0; j < 8; j++) a[j] = 0.0f;

    int i = s;
    for (; i + 4 <= e; i += 4) {
        int c0 = g_cols[i + 0], c1 = g_cols[i + 1];
        int c2 = g_cols[i + 2], c3 = g_cols[i + 3];
        uint4 p0 = __ldg(vh + (size_t)c0 * 5 + f);
        uint4 p1 = __ldg(vh + (size_t)c1 * 5 + f);
        uint4 p2 = __ldg(vh + (size_t)c2 * 5 + f);
        uint4 p3 = __ldg(vh + (size_t)c3 * 5 + f);
        acc8(a, p0); acc8(a, p1); acc8(a, p2); acc8(a, p3);
    }
    for (; i < e; i++) {
        uint4 p = __ldg(vh + (size_t)g_cols[i] * 5 + f);
        acc8(a, p);
    }

    // self-loop term
    {
        uint4 p = __ldg(vh + (size_t)r * 5 + f);
        acc8(a, p);
    }

    const float w = 0.5f * g_dinv[r];
    float4 h0 = __ldg(hf + (size_t)r * 10 + f * 2);
    float4 h1 = __ldg(hf + (size_t)r * 10 + f * 2 + 1);

    float o[8];
    o[0] = w * a[0] + 0.5f * h0.x;
    o[1] = w * a[1] + 0.5f * h0.y;
    o[2] = w * a[2] + 0.5f * h0.z;
    o[3] = w * a[3] + 0.5f * h0.w;
    o[4] = w * a[4] + 0.5f * h1.x;
    o[5] = w * a[5] + 0.5f * h1.y;
    o[6] = w * a[6] + 0.5f * h1.z;
    o[7] = w * a[7] + 0.5f * h1.w;

    if (FINAL) {
        dstf[(size_t)r * 10 + f * 2]     = make_float4(o[0], o[1], o[2], o[3]);
        dstf[(size_t)r * 10 + f * 2 + 1] = make_float4(o[4], o[5], o[6], o[7]);
    } else {
        __half2 q0 = __floats2half2_rn(o[0], o[1]);
        __half2 q1 = __floats2half2_rn(o[2], o[3]);
        __half2 q2 = __floats2half2_rn(o[4], o[5]);
        __half2 q3 = __floats2half2_rn(o[6], o[7]);
        uint4 pk;
        pk.x = *(uint32_t*)&q0; pk.y = *(uint32_t*)&q1;
        pk.z = *(uint32_t*)&q2; pk.w = *(uint32_t*)&q3;
        dsth[(size_t)r * 5 + f] = pk;
    }
}

// ---------------- host ----------------
extern "C" void kernel_launch(void* const* d_in, const int* in_sizes, int n_in,
                              void* d_out, int out_size)
{
    const float* x  = (const float*)d_in[0];
    const int*   ei = (const int*)  d_in[1];
    const float* W1 = (const float*)d_in[2];
    const float* b1 = (const float*)d_in[3];
    const float* W2 = (const float*)d_in[4];
    const float* b2 = (const float*)d_in[5];
    const float* W3 = (const float*)d_in[6];
    const float* b3 = (const float*)d_in[7];
    float* out = (float*)d_out;

    const int* rows = ei;
    const int* cols = ei + N_EDGES;

    void *p;
    float *h1, *h2, *h, *vA, *vB;
    __nv_bfloat16 *w1hi, *w1lo, *w2hi, *w2lo, *w3hi, *w3lo;
    cudaGetSymbolAddress(&p, g_h1);   h1 = (float*)p;
    cudaGetSymbolAddress(&p, g_h2);   h2 = (float*)p;
    cudaGetSymbolAddress(&p, g_h);    h  = (float*)p;
    cudaGetSymbolAddress(&p, g_vA);   vA = (float*)p;
    cudaGetSymbolAddress(&p, g_vB);   vB = (float*)p;
    cudaGetSymbolAddress(&p, g_w1hi); w1hi = (__nv_bfloat16*)p;
    cudaGetSymbolAddress(&p, g_w1lo); w1lo = (__nv_bfloat16*)p;
    cudaGetSymbolAddress(&p, g_w2hi); w2hi = (__nv_bfloat16*)p;
    cudaGetSymbolAddress(&p, g_w2lo); w2lo = (__nv_bfloat16*)p;
    cudaGetSymbolAddress(&p, g_w3hi); w3hi = (__nv_bfloat16*)p;
    cudaGetSymbolAddress(&p, g_w3lo); w3lo = (__nv_bfloat16*)p;

    __nv_bfloat16* h1hi = (__nv_bfloat16*)h1;
    __nv_bfloat16* h1lo = h1hi + (size_t)N_NODES * NHID;
    __nv_bfloat16* h2hi = (__nv_bfloat16*)h2;
    __nv_bfloat16* h2lo = h2hi + (size_t)N_NODES * NHID;

    // side stream + events for CSR/W-split overlap
    cudaStream_t s1;
    cudaStreamCreateWithFlags(&s1, cudaStreamNonBlocking);
    cudaEvent_t evFork, evJoin;
    cudaEventCreateWithFlags(&evFork, cudaEventDisableTiming);
    cudaEventCreateWithFlags(&evJoin, cudaEventDisableTiming);

    // ---- fork: CSR build + w2/w3 splits on side stream ----
    cudaEventRecord(evFork, 0);
    cudaStreamWaitEvent(s1, evFork, 0);
    split_w<<<(NHID * NHID   + 255) / 256, 256, 0, s1>>>(W2, w2hi, w2lo, NHID * NHID);
    split_w<<<(NCLASS * NHID + 255) / 256, 256, 0, s1>>>(W3, w3hi, w3lo, NCLASS * NHID);
    zero_counts  <<<(N_NODES + 255) / 256, 256, 0, s1>>>();
    count_deg    <<<(N_EDGES + 255) / 256, 256, 0, s1>>>(rows);
    compute_dinv <<<(N_NODES + 255) / 256, 256, 0, s1>>>();
    scan_blocks  <<<NBLK, SCAN_T, 0, s1>>>();
    scan_offsets <<<1, 32, 0, s1>>>();
    scan_add     <<<NBLK, SCAN_T, 0, s1>>>();
    scatter_edges<<<(N_EDGES + 255) / 256, 256, 0, s1>>>(rows, cols);
    cudaEventRecord(evJoin, s1);

    // ---- main stream: w1 split + GEMM chain ----
    // (w2/w3 splits finish on s1 long before GEMM2 starts — GEMM1 takes ~150us;
    //  the evJoin wait before propagation is the formal barrier, and GEMM2/3 are
    //  ordered after GEMM1 on stream 0 which started after evFork anyway. To be
    //  strictly safe, GEMM2/3 also wait on evJoin? No: they need w2/w3. Add a
    //  dedicated event right after the splits.)
    split_w<<<(NHID * NFEAT + 255) / 256, 256>>>(W1, w1hi, w1lo, NHID * NFEAT);

    cudaEvent_t evWsplit;
    cudaEventCreateWithFlags(&evWsplit, cudaEventDisableTiming);
    cudaEventRecord(evWsplit, s1);   // after w2/w3 splits queued (they are first on s1)

    const int STG128 = 2 * (128 * RSB) + 2 * (128 * RSB);   // 40960
    const int STG64  = 2 * (128 * RSB) + 2 * (64 * RSB);    // 30720
    const int SMEM_128 = 2 * STG128 + 128 * 4;              // 82432
    const int SMEM_64  = 2 * STG64 + 64 * 4;                // 61696
    cudaFuncSetAttribute((const void*)gemm_hmma<128, 1, 0, 1>,
                         cudaFuncAttributeMaxDynamicSharedMemorySize, SMEM_128);
    cudaFuncSetAttribute((const void*)gemm_hmma<128, 1, 1, 1>,
                         cudaFuncAttributeMaxDynamicSharedMemorySize, SMEM_128);
    cudaFuncSetAttribute((const void*)gemm_hmma<64, 0, 1, 2>,
                         cudaFuncAttributeMaxDynamicSharedMemorySize, SMEM_64);

    const int MG = (N_NODES + 127) / 128;   // 782
    gemm_hmma<128, 1, 0, 1><<<dim3(2, MG), 256, SMEM_128>>>(
        x, nullptr, nullptr, w1hi, w1lo, b1, nullptr, h1hi, h1lo, nullptr,
        N_NODES, NHID, NFEAT);

    // GEMM2 needs w2 split (on s1) — wait on the w-split event
    cudaStreamWaitEvent(0, evWsplit, 0);
    gemm_hmma<128, 1, 1, 1><<<dim3(2, MG), 256, SMEM_128>>>(
        nullptr, h1hi, h1lo, w2hi, w2lo, b2, nullptr, h2hi, h2lo, nullptr,
        N_NODES, NHID, NHID);
    // GEMM3 emits fp32 h AND fp16 v0 (fused h_to_half)
    gemm_hmma<64, 0, 1, 2><<<dim3(1, MG), 256, SMEM_64>>>(
        nullptr, h2hi, h2lo, w3hi, w3lo, b3, h, nullptr, nullptr, (__half*)vA,
        N_NODES, NCLASS, NHID);

    // ---- join: CSR must be done before propagation ----
    cudaStreamWaitEvent(0, evJoin, 0);

    // ---- 10 power iterations (fp16 iterate, fp32 h-term and final) ----
    const int SP_G = (N_NODES * 5 + SPH_T - 1) / SPH_T;   // 1563
    const uint4* src = (const uint4*)vA;
    for (int it = 0; it < 9; it++) {
        uint4* dst = (uint4*)((it & 1) ? vA : vB);
        spmm_h<0><<<SP_G, SPH_T>>>(src, (const float4*)h, dst, nullptr);
        src = dst;
    }
    spmm_h<1><<<SP_G, SPH_T>>>(src, (const float4*)h, nullptr, (float4*)out);
}

// round 14
// speedup vs baseline: 1.3313x; 1.2042x over previous
#include <cuda_runtime.h>
#include <cuda_bf16.h>
#include <cuda_fp16.h>
#include <cstdint>

#define N_NODES 100000
#define N_EDGES 1600000
#define NFEAT   512
#define NHID    256
#define NCLASS  40
#define NF4     (NCLASS / 4)

#define SCAN_T  1024
#define NBLK    ((N_NODES + SCAN_T - 1) / SCAN_T)   // 98

// ---------------- scratch (static device globals; no allocation) ----------------
__device__ float g_h1[(size_t)N_NODES * NHID];   // holds fp16 hi|lo of h1 (aliased)
__device__ float g_h2[(size_t)N_NODES * NHID];   // holds fp16 hi|lo of h2 (aliased)
__device__ float g_h [(size_t)N_NODES * NCLASS];
__device__ __align__(16) float g_vA[(size_t)N_NODES * NCLASS];  // fp16 iterate ping
__device__ __align__(16) float g_vB[(size_t)N_NODES * NCLASS];  // fp16 iterate pong
__device__ float g_dinv[N_NODES];
__device__ int   g_cnt [N_NODES];
__device__ int   g_fill[N_NODES];
__device__ int   g_rowstart[N_NODES + 1];
__device__ int   g_cols[N_EDGES];
__device__ int   g_bsum[128];
// fp16 weights (single-term quantized)
__device__ __align__(16) __half g_w1h[NHID * NFEAT];
__device__ __align__(16) __half g_w2h[NHID * NHID];
__device__ __align__(16) __half g_w3h[NCLASS * NHID];

// ---------------- helpers ----------------
__device__ __forceinline__ uint32_t smem_u32(const void* p) {
    uint32_t a;
    asm("{ .reg .u64 t; cvta.to.shared.u64 t, %1; cvt.u32.u64 %0, t; }" : "=r"(a) : "l"(p));
    return a;
}

__device__ __forceinline__ void mma16816h(float c[4], const uint32_t a[4],
                                          uint32_t b0, uint32_t b1) {
    asm volatile(
        "mma.sync.aligned.m16n8k16.row.col.f32.f16.f16.f32 "
        "{%0,%1,%2,%3}, {%4,%5,%6,%7}, {%8,%9}, {%0,%1,%2,%3};"
        : "+f"(c[0]), "+f"(c[1]), "+f"(c[2]), "+f"(c[3])
        : "r"(a[0]), "r"(a[1]), "r"(a[2]), "r"(a[3]), "r"(b0), "r"(b1));
}

#define LDSM_X4(r0, r1, r2, r3, addr) \
    asm volatile("ldmatrix.sync.aligned.m8n8.x4.shared.b16 {%0,%1,%2,%3}, [%4];" \
                 : "=r"(r0), "=r"(r1), "=r"(r2), "=r"(r3) : "r"(addr))

__device__ __forceinline__ void cp16(uint32_t dst, const void* src, uint32_t bytes) {
    asm volatile("cp.async.cg.shared.global [%0], [%1], 16, %2;"
                 :: "r"(dst), "l"(src), "r"(bytes));
}
#define CP_COMMIT() asm volatile("cp.async.commit_group;" ::: "memory")
#define CP_WAIT(n)  asm volatile("cp.async.wait_group %0;" :: "n"(n) : "memory")

// fp32x4 -> fp16 hi (uint2) + fp16 lo (uint2)
__device__ __forceinline__ void split4h(float4 v, uint2& hi, uint2& lo) {
    __half hx = __float2half_rn(v.x);
    __half hy = __float2half_rn(v.y);
    __half hz = __float2half_rn(v.z);
    __half hw = __float2half_rn(v.w);
    __half lx = __float2half_rn(v.x - __half2float(hx));
    __half ly = __float2half_rn(v.y - __half2float(hy));
    __half lz = __float2half_rn(v.z - __half2float(hz));
    __half lw = __float2half_rn(v.w - __half2float(hw));
    hi.x = ((uint32_t)__half_as_ushort(hy) << 16) | __half_as_ushort(hx);
    hi.y = ((uint32_t)__half_as_ushort(hw) << 16) | __half_as_ushort(hz);
    lo.x = ((uint32_t)__half_as_ushort(ly) << 16) | __half_as_ushort(lx);
    lo.y = ((uint32_t)__half_as_ushort(lw) << 16) | __half_as_ushort(lz);
}

__device__ __forceinline__ void split2h(float2 v, uint32_t& hi, uint32_t& lo) {
    __half hx = __float2half_rn(v.x);
    __half hy = __float2half_rn(v.y);
    __half lx = __float2half_rn(v.x - __half2float(hx));
    __half ly = __float2half_rn(v.y - __half2float(hy));
    hi = ((uint32_t)__half_as_ushort(hy) << 16) | __half_as_ushort(hx);
    lo = ((uint32_t)__half_as_ushort(ly) << 16) | __half_as_ushort(lx);
}

// unpack a uint4 (8 fp16) and accumulate into 8 floats
__device__ __forceinline__ void acc8(float a[8], uint4 p) {
    float2 q;
    q = __half22float2(*(__half2*)&p.x); a[0] += q.x; a[1] += q.y;
    q = __half22float2(*(__half2*)&p.y); a[2] += q.x; a[3] += q.y;
    q = __half22float2(*(__half2*)&p.z); a[4] += q.x; a[5] += q.y;
    q = __half22float2(*(__half2*)&p.w); a[6] += q.x; a[7] += q.y;
}

// ---------------- graph preprocessing ----------------
__global__ void zero_counts() {
    int i = blockIdx.x * blockDim.x + threadIdx.x;
    if (i < N_NODES) { g_cnt[i] = 0; g_fill[i] = 0; }
}
__global__ void count_deg(const int* __restrict__ rows) {
    int e = blockIdx.x * blockDim.x + threadIdx.x;
    if (e < N_EDGES) atomicAdd(&g_cnt[rows[e]], 1);
}
__global__ void compute_dinv() {
    int i = blockIdx.x * blockDim.x + threadIdx.x;
    if (i < N_NODES) g_dinv[i] = 1.0f / (float)(g_cnt[i] + 1);
}
__global__ void scan_blocks() {
    __shared__ int s[SCAN_T];
    int t   = threadIdx.x;
    int gid = blockIdx.x * SCAN_T + t;
    int v   = (gid < N_NODES) ? g_cnt[gid] : 0;
    s[t] = v;
    __syncthreads();
    #pragma unroll
    for (int off = 1; off < SCAN_T; off <<= 1) {
        int x = (t >= off) ? s[t - off] : 0;
        __syncthreads();
        s[t] += x;
        __syncthreads();
    }
    if (gid < N_NODES) g_rowstart[gid] = s[t] - v;
    if (t == SCAN_T - 1) g_bsum[blockIdx.x] = s[t];
}
__global__ void scan_offsets() {
    if (threadIdx.x == 0 && blockIdx.x == 0) {
        int acc = 0;
        for (int i = 0; i < NBLK; i++) { int t = g_bsum[i]; g_bsum[i] = acc; acc += t; }
        g_rowstart[N_NODES] = acc;
    }
}
__global__ void scan_add() {
    int t   = threadIdx.x;
    int gid = blockIdx.x * SCAN_T + t;
    if (gid < N_NODES) g_rowstart[gid] += g_bsum[blockIdx.x];
}
__global__ void scatter_edges(const int* __restrict__ rows, const int* __restrict__ cols) {
    int e = blockIdx.x * blockDim.x + threadIdx.x;
    if (e < N_EDGES) {
        int r   = rows[e];
        int pos = g_rowstart[r] + atomicAdd(&g_fill[r], 1);
        g_cols[pos] = cols[e];
    }
}
__global__ void conv_w(const float* __restrict__ src, __half* __restrict__ dst, int n) {
    int i = blockIdx.x * 256 + threadIdx.x;
    if (i < n) dst[i] = __float2half_rn(src[i]);
}

// ====== HMMA GEMM, fp16 2-term split (A exact = Ahi+Alo, B = fp16(W)) ======
// K-tile 32, 2-stage cp.async pipeline, 2 CTA/SM.
// OUTMODE: 0 = fp32 C only; 1 = fp16 hi/lo (next GEMM layer); 2 = fp32 C + fp16 v0
#define RSB 80             // smem row stride bytes (64B data + 16B pad)

template<int BN, int RELU, int AHL, int OUTMODE>
__global__ __launch_bounds__(256, 2)
void gemm_hmma(const float* __restrict__ Af,
               const __half* __restrict__ Ahi_g,
               const __half* __restrict__ Alo_g,
               const __half* __restrict__ Wh_g,
               const float* __restrict__ bias,
               float* __restrict__ C,
               __half* __restrict__ Chi,
               __half* __restrict__ Clo,
               __half* __restrict__ Chalf,
               int Nrows, int Mcols, int K)
{
    constexpr int NJ      = BN / 16;
    constexpr int ABYTES  = 128 * RSB;                   // 10240
    constexpr int BBYTES  = BN * RSB;
    constexpr int STAGE   = 2 * ABYTES + BBYTES;         // AHI|ALO|BH
    constexpr int OFF_BS  = 2 * STAGE;
    constexpr int BCHUNKS = BN / 64;                     // cp.async 16B iters for B

    extern __shared__ __align__(16) char sm[];

    const uint32_t smb = smem_u32(sm);
    const int tid = threadIdx.x;
    const int wid = tid >> 5;
    const int lid = tid & 31;
    const int warpM = (wid & 3) * 32;
    const int warpN = (wid >> 2) * (BN / 2);
    const int rowBase = blockIdx.y * 128;
    const int colBase = blockIdx.x * BN;
    const int NT = K / 32;

    // bias -> smem
    for (int i = tid; i < BN; i += 256) {
        int gc = colBase + i;
        *(float*)(sm + OFF_BS + i * 4) = (gc < Mcols) ? bias[gc] : 0.0f;
    }

    // per-lane ldmatrix address components
    const int aRow  = (lid & 7) + ((lid >> 3) & 1) * 8;
    const int aColB = (lid >> 4) * 16;
    const int bN    = ((lid >> 4) * 8) + (lid & 7);
    const int bColB = ((lid >> 3) & 1) * 16;

    const uint32_t aAddr0 = smb + (warpM + aRow) * RSB + aColB;
    const uint32_t bAddr0 = smb + 2 * ABYTES + (warpN + bN) * RSB + bColB;

    float acc[2][NJ][4];
    #pragma unroll
    for (int i = 0; i < 2; i++)
        #pragma unroll
        for (int j = 0; j < NJ; j++)
            #pragma unroll
            for (int q = 0; q < 4; q++) acc[i][j][q] = 0.0f;

    float4 paf[4];   // fp32-A prefetch (AHL=0 only)

    // cp.async A (pre-split fp16 hi/lo path)
    auto cpA = [&](int t, int st) {
        const int kt = t * 32;
        char* base = sm + st * STAGE;
        #pragma unroll
        for (int i = 0; i < 2; i++) {
            int idx = tid + i * 256;
            int row = idx >> 2;
            int c   = idx & 3;
            int gr  = rowBase + row;
            uint32_t sz = (gr < Nrows) ? 16u : 0u;
            int gra = (gr < Nrows) ? gr : 0;
            uint32_t so = smem_u32(base + row * RSB + c * 16);
            cp16(so,          Ahi_g + (size_t)gra * K + kt + c * 8, sz);
            cp16(so + ABYTES, Alo_g + (size_t)gra * K + kt + c * 8, sz);
        }
    };
    // cp.async B: BN x 32 fp16 (hi only)
    auto cpB = [&](int t, int st) {
        const int kt = t * 32;
        char* base = sm + st * STAGE + 2 * ABYTES;
        #pragma unroll
        for (int i = 0; i < BCHUNKS; i++) {
            int idx = tid + i * 256;
            int row = idx >> 2;
            int c   = idx & 3;
            int gm  = colBase + row;
            uint32_t sz = (gm < Mcols) ? 16u : 0u;
            int gma = (gm < Mcols) ? gm : 0;
            uint32_t so = smem_u32(base + row * RSB + c * 16);
            cp16(so, Wh_g + (size_t)gma * K + kt + c * 8, sz);
        }
    };
    // fp32 A prefetch to regs (AHL=0): 128x32 fp32, 4 float4/thread
    auto ldA = [&](int t) {
        const int kt = t * 32;
        #pragma unroll
        for (int i = 0; i < 4; i++) {
            int idx = tid + i * 256;
            int row = idx >> 3;
            int c4  = idx & 7;
            int gr  = rowBase + row;
            paf[i] = make_float4(0.f, 0.f, 0.f, 0.f);
            if (gr < Nrows) paf[i] = *(const float4*)(Af + (size_t)gr * K + kt + c4 * 4);
        }
    };
    auto stsA = [&](int st) {
        char* base = sm + st * STAGE;
        #pragma unroll
        for (int i = 0; i < 4; i++) {
            int idx = tid + i * 256;
            int row = idx >> 3;
            int c4  = idx & 7;
            uint2 hi, lo; split4h(paf[i], hi, lo);
            *(uint2*)(base + row * RSB + c4 * 8) = hi;
            *(uint2*)(base + ABYTES + row * RSB + c4 * 8) = lo;
        }
    };

    auto MMA = [&](int st) {
        const uint32_t aA = aAddr0 + st * STAGE;
        const uint32_t bA = bAddr0 + st * STAGE;
        #pragma unroll
        for (int ks = 0; ks < 2; ks++) {
            const uint32_t kOff = ks * 32;
            uint32_t ah[2][4], al[2][4];
            #pragma unroll
            for (int i = 0; i < 2; i++) {
                uint32_t aa = aA + i * 16 * RSB + kOff;
                LDSM_X4(ah[i][0], ah[i][1], ah[i][2], ah[i][3], aa);
                LDSM_X4(al[i][0], al[i][1], al[i][2], al[i][3], aa + ABYTES);
            }
            #pragma unroll
            for (int jp = 0; jp < NJ / 2; jp++) {
                uint32_t bb = bA + jp * 16 * RSB + kOff;
                uint32_t bh0, bh1, bh2, bh3;
                LDSM_X4(bh0, bh1, bh2, bh3, bb);
                #pragma unroll
                for (int i = 0; i < 2; i++) {
                    mma16816h(acc[i][2 * jp],     ah[i], bh0, bh1);
                    mma16816h(acc[i][2 * jp],     al[i], bh0, bh1);
                    mma16816h(acc[i][2 * jp + 1], ah[i], bh2, bh3);
                    mma16816h(acc[i][2 * jp + 1], al[i], bh2, bh3);
                }
            }
        }
    };

    // ---- prologue ----
    if (AHL) cpA(0, 0); else ldA(0);
    cpB(0, 0);
    CP_COMMIT();

    // ---- mainloop ----
    for (int t = 0; t < NT; t++) {
        const int st = t & 1;
        if (!AHL) stsA(st);
        if (t + 1 < NT) {
            const int sn = (t + 1) & 1;
            if (AHL) cpA(t + 1, sn); else ldA(t + 1);
            cpB(t + 1, sn);
        }
        CP_COMMIT();
        if (t + 1 < NT) { CP_WAIT(1); } else { CP_WAIT(0); }
        __syncthreads();
        MMA(st);
        __syncthreads();
    }

    // ---- epilogue ----
    const int rBase = rowBase + warpM + (lid >> 2);
    const int cOff  = warpN + (lid & 3) * 2;
    #pragma unroll
    for (int i = 0; i < 2; i++) {
        #pragma unroll
        for (int j = 0; j < NJ; j++) {
            int cl = cOff + j * 8;
            int gc = colBase + cl;
            if (gc >= Mcols) continue;
            float2 bb = *(const float2*)(sm + OFF_BS + cl * 4);
            int r0 = rBase + i * 16;
            int r1 = r0 + 8;
            float2 v0, v1;
            v0.x = acc[i][j][0] + bb.x; v0.y = acc[i][j][1] + bb.y;
            v1.x = acc[i][j][2] + bb.x; v1.y = acc[i][j][3] + bb.y;
            if (RELU) {
                v0.x = fmaxf(v0.x, 0.f); v0.y = fmaxf(v0.y, 0.f);
                v1.x = fmaxf(v1.x, 0.f); v1.y = fmaxf(v1.y, 0.f);
            }
            if (OUTMODE == 1) {
                uint32_t h0, l0, h1v, l1;
                split2h(v0, h0, l0);
                split2h(v1, h1v, l1);
                if (r0 < Nrows) {
                    *(uint32_t*)(Chi + (size_t)r0 * Mcols + gc) = h0;
                    *(uint32_t*)(Clo + (size_t)r0 * Mcols + gc) = l0;
                }
                if (r1 < Nrows) {
                    *(uint32_t*)(Chi + (size_t)r1 * Mcols + gc) = h1v;
                    *(uint32_t*)(Clo + (size_t)r1 * Mcols + gc) = l1;
                }
            } else {
                if (r0 < Nrows) *(float2*)(C + (size_t)r0 * Mcols + gc) = v0;
                if (r1 < Nrows) *(float2*)(C + (size_t)r1 * Mcols + gc) = v1;
                if (OUTMODE == 2) {
                    __half2 q0 = __floats2half2_rn(v0.x, v0.y);
                    __half2 q1 = __floats2half2_rn(v1.x, v1.y);
                    if (r0 < Nrows) *(uint32_t*)(Chalf + (size_t)r0 * Mcols + gc) = *(uint32_t*)&q0;
                    if (r1 < Nrows) *(uint32_t*)(Chalf + (size_t)r1 * Mcols + gc) = *(uint32_t*)&q1;
                }
            }
        }
    }
}

// ---------------- SpMM power-iteration step, fp16 iterate ----------------
#define SPH_T 320

template<int FINAL>
__global__ __launch_bounds__(SPH_T)
void spmm_h(const uint4* __restrict__ vh,     // fp16 iterate: 5 uint4 per row
            const float4* __restrict__ hf,    // fp32 h: 10 float4 per row
            uint4* __restrict__ dsth,         // fp16 out (FINAL=0)
            float4* __restrict__ dstf)        // fp32 out (FINAL=1)
{
    int t = blockIdx.x * SPH_T + threadIdx.x;
    int r = t / 5;
    int f = t - r * 5;
    if (r >= N_NODES) return;

    const int s = g_rowstart[r];
    const int e = g_rowstart[r + 1];

    float a[8];
    #pragma unroll
    for (int j = 0; j < 8; j++) a[j] = 0.0f;

    int i = s;
    for (; i + 4 <= e; i += 4) {
        int c0 = g_cols[i + 0], c1 = g_cols[i + 1];
        int c2 = g_cols[i + 2], c3 = g_cols[i + 3];
        uint4 p0 = __ldg(vh + (size_t)c0 * 5 + f);
        uint4 p1 = __ldg(vh + (size_t)c1 * 5 + f);
        uint4 p2 = __ldg(vh + (size_t)c2 * 5 + f);
        uint4 p3 = __ldg(vh + (size_t)c3 * 5 + f);
        acc8(a, p0); acc8(a, p1); acc8(a, p2); acc8(a, p3);
    }
    for (; i < e; i++) {
        uint4 p = __ldg(vh + (size_t)g_cols[i] * 5 + f);
        acc8(a, p);
    }

    // self-loop term
    {
        uint4 p = __ldg(vh + (size_t)r * 5 + f);
        acc8(a, p);
    }

    const float w = 0.5f * g_dinv[r];
    float4 h0 = __ldg(hf + (size_t)r * 10 + f * 2);
    float4 h1 = __ldg(hf + (size_t)r * 10 + f * 2 + 1);

    float o[8];
    o[0] = w * a[0] + 0.5f * h0.x;
    o[1] = w * a[1] + 0.5f * h0.y;
    o[2] = w * a[2] + 0.5f * h0.z;
    o[3] = w * a[3] + 0.5f * h0.w;
    o[4] = w * a[4] + 0.5f * h1.x;
    o[5] = w * a[5] + 0.5f * h1.y;
    o[6] = w * a[6] + 0.5f * h1.z;
    o[7] = w * a[7] + 0.5f * h1.w;

    if (FINAL) {
        dstf[(size_t)r * 10 + f * 2]     = make_float4(o[0], o[1], o[2], o[3]);
        dstf[(size_t)r * 10 + f * 2 + 1] = make_float4(o[4], o[5], o[6], o[7]);
    } else {
        __half2 q0 = __floats2half2_rn(o[0], o[1]);
        __half2 q1 = __floats2half2_rn(o[2], o[3]);
        __half2 q2 = __floats2half2_rn(o[4], o[5]);
        __half2 q3 = __floats2half2_rn(o[6], o[7]);
        uint4 pk;
        pk.x = *(uint32_t*)&q0; pk.y = *(uint32_t*)&q1;
        pk.z = *(uint32_t*)&q2; pk.w = *(uint32_t*)&q3;
        dsth[(size_t)r * 5 + f] = pk;
    }
}

// ---------------- host ----------------
extern "C" void kernel_launch(void* const* d_in, const int* in_sizes, int n_in,
                              void* d_out, int out_size)
{
    const float* x  = (const float*)d_in[0];
    const int*   ei = (const int*)  d_in[1];
    const float* W1 = (const float*)d_in[2];
    const float* b1 = (const float*)d_in[3];
    const float* W2 = (const float*)d_in[4];
    const float* b2 = (const float*)d_in[5];
    const float* W3 = (const float*)d_in[6];
    const float* b3 = (const float*)d_in[7];
    float* out = (float*)d_out;

    const int* rows = ei;
    const int* cols = ei + N_EDGES;

    void *p;
    float *h1, *h2, *h, *vA, *vB;
    __half *w1h, *w2h, *w3h;
    cudaGetSymbolAddress(&p, g_h1);  h1 = (float*)p;
    cudaGetSymbolAddress(&p, g_h2);  h2 = (float*)p;
    cudaGetSymbolAddress(&p, g_h);   h  = (float*)p;
    cudaGetSymbolAddress(&p, g_vA);  vA = (float*)p;
    cudaGetSymbolAddress(&p, g_vB);  vB = (float*)p;
    cudaGetSymbolAddress(&p, g_w1h); w1h = (__half*)p;
    cudaGetSymbolAddress(&p, g_w2h); w2h = (__half*)p;
    cudaGetSymbolAddress(&p, g_w3h); w3h = (__half*)p;

    __half* h1hi = (__half*)h1;
    __half* h1lo = h1hi + (size_t)N_NODES * NHID;
    __half* h2hi = (__half*)h2;
    __half* h2lo = h2hi + (size_t)N_NODES * NHID;

    // side stream + events for CSR/W-conv overlap
    cudaStream_t s1;
    cudaStreamCreateWithFlags(&s1, cudaStreamNonBlocking);
    cudaEvent_t evFork, evJoin, evW;
    cudaEventCreateWithFlags(&evFork, cudaEventDisableTiming);
    cudaEventCreateWithFlags(&evJoin, cudaEventDisableTiming);
    cudaEventCreateWithFlags(&evW, cudaEventDisableTiming);

    // ---- fork: w2/w3 conv + CSR build on side stream ----
    cudaEventRecord(evFork, 0);
    cudaStreamWaitEvent(s1, evFork, 0);
    conv_w<<<(NHID * NHID   + 255) / 256, 256, 0, s1>>>(W2, w2h, NHID * NHID);
    conv_w<<<(NCLASS * NHID + 255) / 256, 256, 0, s1>>>(W3, w3h, NCLASS * NHID);
    cudaEventRecord(evW, s1);
    zero_counts  <<<(N_NODES + 255) / 256, 256, 0, s1>>>();
    count_deg    <<<(N_EDGES + 255) / 256, 256, 0, s1>>>(rows);
    compute_dinv <<<(N_NODES + 255) / 256, 256, 0, s1>>>();
    scan_blocks  <<<NBLK, SCAN_T, 0, s1>>>();
    scan_offsets <<<1, 32, 0, s1>>>();
    scan_add     <<<NBLK, SCAN_T, 0, s1>>>();
    scatter_edges<<<(N_EDGES + 255) / 256, 256, 0, s1>>>(rows, cols);
    cudaEventRecord(evJoin, s1);

    // ---- main stream: w1 conv + GEMM chain ----
    conv_w<<<(NHID * NFEAT + 255) / 256, 256>>>(W1, w1h, NHID * NFEAT);

    const int STG128 = 2 * (128 * RSB) + 128 * RSB;   // 30720
    const int STG64  = 2 * (128 * RSB) + 64 * RSB;    // 25600
    const int SMEM_128 = 2 * STG128 + 128 * 4;        // 61952
    const int SMEM_64  = 2 * STG64 + 64 * 4;          // 51456
    cudaFuncSetAttribute((const void*)gemm_hmma<128, 1, 0, 1>,
                         cudaFuncAttributeMaxDynamicSharedMemorySize, SMEM_128);
    cudaFuncSetAttribute((const void*)gemm_hmma<128, 1, 1, 1>,
                         cudaFuncAttributeMaxDynamicSharedMemorySize, SMEM_128);
    cudaFuncSetAttribute((const void*)gemm_hmma<64, 0, 1, 2>,
                         cudaFuncAttributeMaxDynamicSharedMemorySize, SMEM_64);

    const int MG = (N_NODES + 127) / 128;   // 782
    gemm_hmma<128, 1, 0, 1><<<dim3(2, MG), 256, SMEM_128>>>(
        x, nullptr, nullptr, w1h, b1, nullptr, h1hi, h1lo, nullptr,
        N_NODES, NHID, NFEAT);

    // GEMM2/3 need w2/w3 conv (on s1)
    cudaStreamWaitEvent(0, evW, 0);
    gemm_hmma<128, 1, 1, 1><<<dim3(2, MG), 256, SMEM_128>>>(
        nullptr, h1hi, h1lo, w2h, b2, nullptr, h2hi, h2lo, nullptr,
        N_NODES, NHID, NHID);
    // GEMM3 emits fp32 h AND fp16 v0 (fused)
    gemm_hmma<64, 0, 1, 2><<<dim3(1, MG), 256, SMEM_64>>>(
        nullptr, h2hi, h2lo, w3h, b3, h, nullptr, nullptr, (__half*)vA,
        N_NODES, NCLASS, NHID);

    // ---- join: CSR must be done before propagation ----
    cudaStreamWaitEvent(0, evJoin, 0);

    // ---- 10 power iterations (fp16 iterate, fp32 h-term and final) ----
    const int SP_G = (N_NODES * 5 + SPH_T - 1) / SPH_T;   // 1563
    const uint4* src = (const uint4*)vA;
    for (int it = 0; it < 9; it++) {
        uint4* dst = (uint4*)((it & 1) ? vA : vB);
        spmm_h<0><<<SP_G, SPH_T>>>(src, (const float4*)h, dst, nullptr);
        src = dst;
    }
    spmm_h<1><<<SP_G, SPH_T>>>(src, (const float4*)h, nullptr, (float4*)out);
}

// round 15
// speedup vs baseline: 1.4460x; 1.0862x over previous
#include <cuda_runtime.h>
#include <cuda_bf16.h>
#include <cuda_fp16.h>
#include <cstdint>

#define N_NODES 100000
#define N_EDGES 1600000
#define NFEAT   512
#define NHID    256
#define NCLASS  40
#define NF4     (NCLASS / 4)

#define SCAN_T  1024
#define NBLK    ((N_NODES + SCAN_T - 1) / SCAN_T)   // 98

// ---------------- scratch (static device globals; no allocation) ----------------
__device__ float g_h1[(size_t)N_NODES * NHID];   // holds fp16 hi|lo of h1 (aliased)
__device__ float g_h2[(size_t)N_NODES * NHID];   // holds fp16 hi|lo of h2 (aliased)
__device__ float g_h [(size_t)N_NODES * NCLASS];
__device__ __align__(16) float g_vA[(size_t)N_NODES * NCLASS];  // fp16 iterate ping
__device__ __align__(16) float g_vB[(size_t)N_NODES * NCLASS];  // fp16 iterate pong
__device__ float g_dinv[N_NODES];
__device__ int   g_cnt [N_NODES];
__device__ int   g_fill[N_NODES];
__device__ int   g_rowstart[N_NODES + 1];
__device__ int   g_cols[N_EDGES];
__device__ int   g_bsum[128];
// fp16 weights (single-term quantized)
__device__ __align__(16) __half g_w1h[NHID * NFEAT];
__device__ __align__(16) __half g_w2h[NHID * NHID];
__device__ __align__(16) __half g_w3h[NCLASS * NHID];

// ---------------- helpers ----------------
__device__ __forceinline__ uint32_t smem_u32(const void* p) {
    uint32_t a;
    asm("{ .reg .u64 t; cvta.to.shared.u64 t, %1; cvt.u32.u64 %0, t; }" : "=r"(a) : "l"(p));
    return a;
}

__device__ __forceinline__ void mma16816h(float c[4], const uint32_t a[4],
                                          uint32_t b0, uint32_t b1) {
    asm volatile(
        "mma.sync.aligned.m16n8k16.row.col.f32.f16.f16.f32 "
        "{%0,%1,%2,%3}, {%4,%5,%6,%7}, {%8,%9}, {%0,%1,%2,%3};"
        : "+f"(c[0]), "+f"(c[1]), "+f"(c[2]), "+f"(c[3])
        : "r"(a[0]), "r"(a[1]), "r"(a[2]), "r"(a[3]), "r"(b0), "r"(b1));
}

#define LDSM_X4(r0, r1, r2, r3, addr) \
    asm volatile("ldmatrix.sync.aligned.m8n8.x4.shared.b16 {%0,%1,%2,%3}, [%4];" \
                 : "=r"(r0), "=r"(r1), "=r"(r2), "=r"(r3) : "r"(addr))

__device__ __forceinline__ void cp16(uint32_t dst, const void* src, uint32_t bytes) {
    asm volatile("cp.async.cg.shared.global [%0], [%1], 16, %2;"
                 :: "r"(dst), "l"(src), "r"(bytes));
}
#define CP_COMMIT() asm volatile("cp.async.commit_group;" ::: "memory")
#define CP_WAIT(n)  asm volatile("cp.async.wait_group %0;" :: "n"(n) : "memory")

// fp32x4 -> fp16 hi (uint2) + fp16 lo (uint2)
__device__ __forceinline__ void split4h(float4 v, uint2& hi, uint2& lo) {
    __half hx = __float2half_rn(v.x);
    __half hy = __float2half_rn(v.y);
    __half hz = __float2half_rn(v.z);
    __half hw = __float2half_rn(v.w);
    __half lx = __float2half_rn(v.x - __half2float(hx));
    __half ly = __float2half_rn(v.y - __half2float(hy));
    __half lz = __float2half_rn(v.z - __half2float(hz));
    __half lw = __float2half_rn(v.w - __half2float(hw));
    hi.x = ((uint32_t)__half_as_ushort(hy) << 16) | __half_as_ushort(hx);
    hi.y = ((uint32_t)__half_as_ushort(hw) << 16) | __half_as_ushort(hz);
    lo.x = ((uint32_t)__half_as_ushort(ly) << 16) | __half_as_ushort(lx);
    lo.y = ((uint32_t)__half_as_ushort(lw) << 16) | __half_as_ushort(lz);
}

// fp32x4 -> fp16 hi only
__device__ __forceinline__ uint2 pack4h(float4 v) {
    __half2 a = __floats2half2_rn(v.x, v.y);
    __half2 b = __floats2half2_rn(v.z, v.w);
    uint2 r;
    r.x = *(uint32_t*)&a;
    r.y = *(uint32_t*)&b;
    return r;
}

__device__ __forceinline__ void split2h(float2 v, uint32_t& hi, uint32_t& lo) {
    __half hx = __float2half_rn(v.x);
    __half hy = __float2half_rn(v.y);
    __half lx = __float2half_rn(v.x - __half2float(hx));
    __half ly = __float2half_rn(v.y - __half2float(hy));
    hi = ((uint32_t)__half_as_ushort(hy) << 16) | __half_as_ushort(hx);
    lo = ((uint32_t)__half_as_ushort(ly) << 16) | __half_as_ushort(lx);
}

// unpack a uint4 (8 fp16) and accumulate into 8 floats
__device__ __forceinline__ void acc8(float a[8], uint4 p) {
    float2 q;
    q = __half22float2(*(__half2*)&p.x); a[0] += q.x; a[1] += q.y;
    q = __half22float2(*(__half2*)&p.y); a[2] += q.x; a[3] += q.y;
    q = __half22float2(*(__half2*)&p.z); a[4] += q.x; a[5] += q.y;
    q = __half22float2(*(__half2*)&p.w); a[6] += q.x; a[7] += q.y;
}

// ---------------- graph preprocessing ----------------
__global__ void zero_counts() {
    int i = blockIdx.x * blockDim.x + threadIdx.x;
    if (i < N_NODES) { g_cnt[i] = 0; g_fill[i] = 0; }
}
__global__ void count_deg(const int* __restrict__ rows) {
    int e = blockIdx.x * blockDim.x + threadIdx.x;
    if (e < N_EDGES) atomicAdd(&g_cnt[rows[e]], 1);
}
__global__ void compute_dinv() {
    int i = blockIdx.x * blockDim.x + threadIdx.x;
    if (i < N_NODES) g_dinv[i] = 1.0f / (float)(g_cnt[i] + 1);
}
__global__ void scan_blocks() {
    __shared__ int s[SCAN_T];
    int t   = threadIdx.x;
    int gid = blockIdx.x * SCAN_T + t;
    int v   = (gid < N_NODES) ? g_cnt[gid] : 0;
    s[t] = v;
    __syncthreads();
    #pragma unroll
    for (int off = 1; off < SCAN_T; off <<= 1) {
        int x = (t >= off) ? s[t - off] : 0;
        __syncthreads();
        s[t] += x;
        __syncthreads();
    }
    if (gid < N_NODES) g_rowstart[gid] = s[t] - v;
    if (t == SCAN_T - 1) g_bsum[blockIdx.x] = s[t];
}
__global__ void scan_offsets() {
    if (threadIdx.x == 0 && blockIdx.x == 0) {
        int acc = 0;
        for (int i = 0; i < NBLK; i++) { int t = g_bsum[i]; g_bsum[i] = acc; acc += t; }
        g_rowstart[N_NODES] = acc;
    }
}
__global__ void scan_add() {
    int t   = threadIdx.x;
    int gid = blockIdx.x * SCAN_T + t;
    if (gid < N_NODES) g_rowstart[gid] += g_bsum[blockIdx.x];
}
__global__ void scatter_edges(const int* __restrict__ rows, const int* __restrict__ cols) {
    int e = blockIdx.x * blockDim.x + threadIdx.x;
    if (e < N_EDGES) {
        int r   = rows[e];
        int pos = g_rowstart[r] + atomicAdd(&g_fill[r], 1);
        g_cols[pos] = cols[e];
    }
}
__global__ void conv_w(const float* __restrict__ src, __half* __restrict__ dst, int n) {
    int i = blockIdx.x * 256 + threadIdx.x;
    if (i < n) dst[i] = __float2half_rn(src[i]);
}

// ====== HMMA GEMM, fp16 split, K-tile 32, 2-stage cp.async pipeline ======
// ATERMS: 1 = A quantized to single fp16 term; 2 = A exact (hi+lo)
// OUTMODE: 0 = fp32 C only; 1 = fp16 hi/lo (next GEMM layer); 2 = fp32 C + fp16 v0
#define RSB 80             // smem row stride bytes (64B data + 16B pad)

template<int BN, int RELU, int AHL, int OUTMODE, int ATERMS>
__global__ __launch_bounds__(256, 2)
void gemm_hmma(const float* __restrict__ Af,
               const __half* __restrict__ Ahi_g,
               const __half* __restrict__ Alo_g,
               const __half* __restrict__ Wh_g,
               const float* __restrict__ bias,
               float* __restrict__ C,
               __half* __restrict__ Chi,
               __half* __restrict__ Clo,
               __half* __restrict__ Chalf,
               int Nrows, int Mcols, int K)
{
    constexpr int NJ      = BN / 16;
    constexpr int ABYTES  = 128 * RSB;                   // 10240
    constexpr int BBYTES  = BN * RSB;
    constexpr int STAGE   = ATERMS * ABYTES + BBYTES;    // AHI[|ALO]|BH
    constexpr int OFF_BS  = 2 * STAGE;
    constexpr int BCHUNKS = BN / 64;                     // cp.async 16B iters for B

    extern __shared__ __align__(16) char sm[];

    const uint32_t smb = smem_u32(sm);
    const int tid = threadIdx.x;
    const int wid = tid >> 5;
    const int lid = tid & 31;
    const int warpM = (wid & 3) * 32;
    const int warpN = (wid >> 2) * (BN / 2);
    const int rowBase = blockIdx.y * 128;
    const int colBase = blockIdx.x * BN;
    const int NT = K / 32;

    // bias -> smem
    for (int i = tid; i < BN; i += 256) {
        int gc = colBase + i;
        *(float*)(sm + OFF_BS + i * 4) = (gc < Mcols) ? bias[gc] : 0.0f;
    }

    // per-lane ldmatrix address components
    const int aRow  = (lid & 7) + ((lid >> 3) & 1) * 8;
    const int aColB = (lid >> 4) * 16;
    const int bN    = ((lid >> 4) * 8) + (lid & 7);
    const int bColB = ((lid >> 3) & 1) * 16;

    const uint32_t aAddr0 = smb + (warpM + aRow) * RSB + aColB;
    const uint32_t bAddr0 = smb + ATERMS * ABYTES + (warpN + bN) * RSB + bColB;

    float acc[2][NJ][4];
    #pragma unroll
    for (int i = 0; i < 2; i++)
        #pragma unroll
        for (int j = 0; j < NJ; j++)
            #pragma unroll
            for (int q = 0; q < 4; q++) acc[i][j][q] = 0.0f;

    float4 paf[4];   // fp32-A prefetch (AHL=0 only)

    // cp.async A (pre-split fp16 hi/lo path; ATERMS==2 only)
    auto cpA = [&](int t, int st) {
        const int kt = t * 32;
        char* base = sm + st * STAGE;
        #pragma unroll
        for (int i = 0; i < 2; i++) {
            int idx = tid + i * 256;
            int row = idx >> 2;
            int c   = idx & 3;
            int gr  = rowBase + row;
            uint32_t sz = (gr < Nrows) ? 16u : 0u;
            int gra = (gr < Nrows) ? gr : 0;
            uint32_t so = smem_u32(base + row * RSB + c * 16);
            cp16(so, Ahi_g + (size_t)gra * K + kt + c * 8, sz);
            if (ATERMS == 2)
                cp16(so + ABYTES, Alo_g + (size_t)gra * K + kt + c * 8, sz);
        }
    };
    // cp.async B: BN x 32 fp16
    auto cpB = [&](int t, int st) {
        const int kt = t * 32;
        char* base = sm + st * STAGE + ATERMS * ABYTES;
        #pragma unroll
        for (int i = 0; i < BCHUNKS; i++) {
            int idx = tid + i * 256;
            int row = idx >> 2;
            int c   = idx & 3;
            int gm  = colBase + row;
            uint32_t sz = (gm < Mcols) ? 16u : 0u;
            int gma = (gm < Mcols) ? gm : 0;
            uint32_t so = smem_u32(base + row * RSB + c * 16);
            cp16(so, Wh_g + (size_t)gma * K + kt + c * 8, sz);
        }
    };
    // fp32 A prefetch to regs (AHL=0): 128x32 fp32, 4 float4/thread
    auto ldA = [&](int t) {
        const int kt = t * 32;
        #pragma unroll
        for (int i = 0; i < 4; i++) {
            int idx = tid + i * 256;
            int row = idx >> 3;
            int c4  = idx & 7;
            int gr  = rowBase + row;
            paf[i] = make_float4(0.f, 0.f, 0.f, 0.f);
            if (gr < Nrows) paf[i] = *(const float4*)(Af + (size_t)gr * K + kt + c4 * 4);
        }
    };
    auto stsA = [&](int st) {
        char* base = sm + st * STAGE;
        #pragma unroll
        for (int i = 0; i < 4; i++) {
            int idx = tid + i * 256;
            int row = idx >> 3;
            int c4  = idx & 7;
            if (ATERMS == 2) {
                uint2 hi, lo; split4h(paf[i], hi, lo);
                *(uint2*)(base + row * RSB + c4 * 8) = hi;
                *(uint2*)(base + ABYTES + row * RSB + c4 * 8) = lo;
            } else {
                *(uint2*)(base + row * RSB + c4 * 8) = pack4h(paf[i]);
            }
        }
    };

    auto MMA = [&](int st) {
        const uint32_t aA = aAddr0 + st * STAGE;
        const uint32_t bA = bAddr0 + st * STAGE;
        #pragma unroll
        for (int ks = 0; ks < 2; ks++) {
            const uint32_t kOff = ks * 32;
            uint32_t ah[2][4], al[2][4];
            #pragma unroll
            for (int i = 0; i < 2; i++) {
                uint32_t aa = aA + i * 16 * RSB + kOff;
                LDSM_X4(ah[i][0], ah[i][1], ah[i][2], ah[i][3], aa);
                if (ATERMS == 2)
                    LDSM_X4(al[i][0], al[i][1], al[i][2], al[i][3], aa + ABYTES);
            }
            #pragma unroll
            for (int jp = 0; jp < NJ / 2; jp++) {
                uint32_t bb = bA + jp * 16 * RSB + kOff;
                uint32_t bh0, bh1, bh2, bh3;
                LDSM_X4(bh0, bh1, bh2, bh3, bb);
                #pragma unroll
                for (int i = 0; i < 2; i++) {
                    mma16816h(acc[i][2 * jp],     ah[i], bh0, bh1);
                    mma16816h(acc[i][2 * jp + 1], ah[i], bh2, bh3);
                    if (ATERMS == 2) {
                        mma16816h(acc[i][2 * jp],     al[i], bh0, bh1);
                        mma16816h(acc[i][2 * jp + 1], al[i], bh2, bh3);
                    }
                }
            }
        }
    };

    // ---- prologue ----
    if (AHL) cpA(0, 0); else ldA(0);
    cpB(0, 0);
    CP_COMMIT();

    // ---- mainloop ----
    for (int t = 0; t < NT; t++) {
        const int st = t & 1;
        if (!AHL) stsA(st);
        if (t + 1 < NT) {
            const int sn = (t + 1) & 1;
            if (AHL) cpA(t + 1, sn); else ldA(t + 1);
            cpB(t + 1, sn);
        }
        CP_COMMIT();
        if (t + 1 < NT) { CP_WAIT(1); } else { CP_WAIT(0); }
        __syncthreads();
        MMA(st);
        __syncthreads();
    }

    // ---- epilogue ----
    const int rBase = rowBase + warpM + (lid >> 2);
    const int cOff  = warpN + (lid & 3) * 2;
    #pragma unroll
    for (int i = 0; i < 2; i++) {
        #pragma unroll
        for (int j = 0; j < NJ; j++) {
            int cl = cOff + j * 8;
            int gc = colBase + cl;
            if (gc >= Mcols) continue;
            float2 bb = *(const float2*)(sm + OFF_BS + cl * 4);
            int r0 = rBase + i * 16;
            int r1 = r0 + 8;
            float2 v0, v1;
            v0.x = acc[i][j][0] + bb.x; v0.y = acc[i][j][1] + bb.y;
            v1.x = acc[i][j][2] + bb.x; v1.y = acc[i][j][3] + bb.y;
            if (RELU) {
                v0.x = fmaxf(v0.x, 0.f); v0.y = fmaxf(v0.y, 0.f);
                v1.x = fmaxf(v1.x, 0.f); v1.y = fmaxf(v1.y, 0.f);
            }
            if (OUTMODE == 1) {
                uint32_t h0, l0, h1v, l1;
                split2h(v0, h0, l0);
                split2h(v1, h1v, l1);
                if (r0 < Nrows) {
                    *(uint32_t*)(Chi + (size_t)r0 * Mcols + gc) = h0;
                    *(uint32_t*)(Clo + (size_t)r0 * Mcols + gc) = l0;
                }
                if (r1 < Nrows) {
                    *(uint32_t*)(Chi + (size_t)r1 * Mcols + gc) = h1v;
                    *(uint32_t*)(Clo + (size_t)r1 * Mcols + gc) = l1;
                }
            } else {
                if (r0 < Nrows) *(float2*)(C + (size_t)r0 * Mcols + gc) = v0;
                if (r1 < Nrows) *(float2*)(C + (size_t)r1 * Mcols + gc) = v1;
                if (OUTMODE == 2) {
                    __half2 q0 = __floats2half2_rn(v0.x, v0.y);
                    __half2 q1 = __floats2half2_rn(v1.x, v1.y);
                    if (r0 < Nrows) *(uint32_t*)(Chalf + (size_t)r0 * Mcols + gc) = *(uint32_t*)&q0;
                    if (r1 < Nrows) *(uint32_t*)(Chalf + (size_t)r1 * Mcols + gc) = *(uint32_t*)&q1;
                }
            }
        }
    }
}

// ---------------- SpMM power-iteration step, fp16 iterate ----------------
#define SPH_T 320

template<int FINAL>
__global__ __launch_bounds__(SPH_T)
void spmm_h(const uint4* __restrict__ vh,     // fp16 iterate: 5 uint4 per row
            const float4* __restrict__ hf,    // fp32 h: 10 float4 per row
            uint4* __restrict__ dsth,         // fp16 out (FINAL=0)
            float4* __restrict__ dstf)        // fp32 out (FINAL=1)
{
    int t = blockIdx.x * SPH_T + threadIdx.x;
    int r = t / 5;
    int f = t - r * 5;
    if (r >= N_NODES) return;

    const int s = g_rowstart[r];
    const int e = g_rowstart[r + 1];

    float a[8];
    #pragma unroll
    for (int j = 0; j < 8; j++) a[j] = 0.0f;

    int i = s;
    for (; i + 4 <= e; i += 4) {
        int c0 = g_cols[i + 0], c1 = g_cols[i + 1];
        int c2 = g_cols[i + 2], c3 = g_cols[i + 3];
        uint4 p0 = __ldg(vh + (size_t)c0 * 5 + f);
        uint4 p1 = __ldg(vh + (size_t)c1 * 5 + f);
        uint4 p2 = __ldg(vh + (size_t)c2 * 5 + f);
        uint4 p3 = __ldg(vh + (size_t)c3 * 5 + f);
        acc8(a, p0); acc8(a, p1); acc8(a, p2); acc8(a, p3);
    }
    for (; i < e; i++) {
        uint4 p = __ldg(vh + (size_t)g_cols[i] * 5 + f);
        acc8(a, p);
    }

    // self-loop term
    {
        uint4 p = __ldg(vh + (size_t)r * 5 + f);
        acc8(a, p);
    }

    const float w = 0.5f * g_dinv[r];
    float4 h0 = __ldg(hf + (size_t)r * 10 + f * 2);
    float4 h1 = __ldg(hf + (size_t)r * 10 + f * 2 + 1);

    float o[8];
    o[0] = w * a[0] + 0.5f * h0.x;
    o[1] = w * a[1] + 0.5f * h0.y;
    o[2] = w * a[2] + 0.5f * h0.z;
    o[3] = w * a[3] + 0.5f * h0.w;
    o[4] = w * a[4] + 0.5f * h1.x;
    o[5] = w * a[5] + 0.5f * h1.y;
    o[6] = w * a[6] + 0.5f * h1.z;
    o[7] = w * a[7] + 0.5f * h1.w;

    if (FINAL) {
        dstf[(size_t)r * 10 + f * 2]     = make_float4(o[0], o[1], o[2], o[3]);
        dstf[(size_t)r * 10 + f * 2 + 1] = make_float4(o[4], o[5], o[6], o[7]);
    } else {
        __half2 q0 = __floats2half2_rn(o[0], o[1]);
        __half2 q1 = __floats2half2_rn(o[2], o[3]);
        __half2 q2 = __floats2half2_rn(o[4], o[5]);
        __half2 q3 = __floats2half2_rn(o[6], o[7]);
        uint4 pk;
        pk.x = *(uint32_t*)&q0; pk.y = *(uint32_t*)&q1;
        pk.z = *(uint32_t*)&q2; pk.w = *(uint32_t*)&q3;
        dsth[(size_t)r * 5 + f] = pk;
    }
}

// ---------------- host ----------------
extern "C" void kernel_launch(void* const* d_in, const int* in_sizes, int n_in,
                              void* d_out, int out_size)
{
    const float* x  = (const float*)d_in[0];
    const int*   ei = (const int*)  d_in[1];
    const float* W1 = (const float*)d_in[2];
    const float* b1 = (const float*)d_in[3];
    const float* W2 = (const float*)d_in[4];
    const float* b2 = (const float*)d_in[5];
    const float* W3 = (const float*)d_in[6];
    const float* b3 = (const float*)d_in[7];
    float* out = (float*)d_out;

    const int* rows = ei;
    const int* cols = ei + N_EDGES;

    void *p;
    float *h1, *h2, *h, *vA, *vB;
    __half *w1h, *w2h, *w3h;
    cudaGetSymbolAddress(&p, g_h1);  h1 = (float*)p;
    cudaGetSymbolAddress(&p, g_h2);  h2 = (float*)p;
    cudaGetSymbolAddress(&p, g_h);   h  = (float*)p;
    cudaGetSymbolAddress(&p, g_vA);  vA = (float*)p;
    cudaGetSymbolAddress(&p, g_vB);  vB = (float*)p;
    cudaGetSymbolAddress(&p, g_w1h); w1h = (__half*)p;
    cudaGetSymbolAddress(&p, g_w2h); w2h = (__half*)p;
    cudaGetSymbolAddress(&p, g_w3h); w3h = (__half*)p;

    __half* h1hi = (__half*)h1;
    __half* h1lo = h1hi + (size_t)N_NODES * NHID;
    __half* h2hi = (__half*)h2;
    __half* h2lo = h2hi + (size_t)N_NODES * NHID;

    // side stream + events for CSR/W-conv overlap
    cudaStream_t s1;
    cudaStreamCreateWithFlags(&s1, cudaStreamNonBlocking);
    cudaEvent_t evFork, evJoin, evW;
    cudaEventCreateWithFlags(&evFork, cudaEventDisableTiming);
    cudaEventCreateWithFlags(&evJoin, cudaEventDisableTiming);
    cudaEventCreateWithFlags(&evW, cudaEventDisableTiming);

    // ---- fork: w2/w3 conv + CSR build on side stream ----
    cudaEventRecord(evFork, 0);
    cudaStreamWaitEvent(s1, evFork, 0);
    conv_w<<<(NHID * NHID   + 255) / 256, 256, 0, s1>>>(W2, w2h, NHID * NHID);
    conv_w<<<(NCLASS * NHID + 255) / 256, 256, 0, s1>>>(W3, w3h, NCLASS * NHID);
    cudaEventRecord(evW, s1);
    zero_counts  <<<(N_NODES + 255) / 256, 256, 0, s1>>>();
    count_deg    <<<(N_EDGES + 255) / 256, 256, 0, s1>>>(rows);
    compute_dinv <<<(N_NODES + 255) / 256, 256, 0, s1>>>();
    scan_blocks  <<<NBLK, SCAN_T, 0, s1>>>();
    scan_offsets <<<1, 32, 0, s1>>>();
    scan_add     <<<NBLK, SCAN_T, 0, s1>>>();
    scatter_edges<<<(N_EDGES + 255) / 256, 256, 0, s1>>>(rows, cols);
    cudaEventRecord(evJoin, s1);

    // ---- main stream: w1 conv + GEMM chain ----
    conv_w<<<(NHID * NFEAT + 255) / 256, 256>>>(W1, w1h, NHID * NFEAT);

    const int STG1   = 128 * RSB + 128 * RSB;            // 20480 (ATERMS=1)
    const int STG128 = 2 * (128 * RSB) + 128 * RSB;      // 30720 (ATERMS=2)
    const int STG64  = 2 * (128 * RSB) + 64 * RSB;       // 25600
    const int SMEM_1   = 2 * STG1 + 128 * 4;             // 41472
    const int SMEM_128 = 2 * STG128 + 128 * 4;           // 61952
    const int SMEM_64  = 2 * STG64 + 64 * 4;             // 51456
    cudaFuncSetAttribute((const void*)gemm_hmma<128, 1, 0, 1, 1>,
                         cudaFuncAttributeMaxDynamicSharedMemorySize, SMEM_1);
    cudaFuncSetAttribute((const void*)gemm_hmma<128, 1, 1, 1, 2>,
                         cudaFuncAttributeMaxDynamicSharedMemorySize, SMEM_128);
    cudaFuncSetAttribute((const void*)gemm_hmma<64, 0, 1, 2, 2>,
                         cudaFuncAttributeMaxDynamicSharedMemorySize, SMEM_64);

    const int MG = (N_NODES + 127) / 128;   // 782
    // GEMM1: A = fp16(x), single term
    gemm_hmma<128, 1, 0, 1, 1><<<dim3(2, MG), 256, SMEM_1>>>(
        x, nullptr, nullptr, w1h, b1, nullptr, h1hi, h1lo, nullptr,
        N_NODES, NHID, NFEAT);

    // GEMM2/3 need w2/w3 conv (on s1); A exact 2-term
    cudaStreamWaitEvent(0, evW, 0);
    gemm_hmma<128, 1, 1, 1, 2><<<dim3(2, MG), 256, SMEM_128>>>(
        nullptr, h1hi, h1lo, w2h, b2, nullptr, h2hi, h2lo, nullptr,
        N_NODES, NHID, NHID);
    // GEMM3 emits fp32 h AND fp16 v0 (fused)
    gemm_hmma<64, 0, 1, 2, 2><<<dim3(1, MG), 256, SMEM_64>>>(
        nullptr, h2hi, h2lo, w3h, b3, h, nullptr, nullptr, (__half*)vA,
        N_NODES, NCLASS, NHID);

    // ---- join: CSR must be done before propagation ----
    cudaStreamWaitEvent(0, evJoin, 0);

    // ---- 10 power iterations (fp16 iterate, fp32 h-term and final) ----
    const int SP_G = (N_NODES * 5 + SPH_T - 1) / SPH_T;   // 1563
    const uint4* src = (const uint4*)vA;
    for (int it = 0; it < 9; it++) {
        uint4* dst = (uint4*)((it & 1) ? vA : vB);
        spmm_h<0><<<SP_G, SPH_T>>>(src, (const float4*)h, dst, nullptr);
        src = dst;
    }
    spmm_h<1><<<SP_G, SPH_T>>>(src, (const float4*)h, nullptr, (float4*)out);
}

// round 16
// speedup vs baseline: 1.6283x; 1.1260x over previous
#include <cuda_runtime.h>
#include <cuda_bf16.h>
#include <cuda_fp16.h>
#include <cstdint>

#define N_NODES 100000
#define N_EDGES 1600000
#define NFEAT   512
#define NHID    256
#define NCLASS  40
#define NF4     (NCLASS / 4)

#define SCAN_T  1024
#define NBLK    ((N_NODES + SCAN_T - 1) / SCAN_T)   // 98

// ---------------- scratch (static device globals; no allocation) ----------------
__device__ float g_h1[(size_t)N_NODES * NHID];   // holds fp16 h1 (single term, aliased)
__device__ float g_h2[(size_t)N_NODES * NHID];   // holds fp16 hi|lo of h2 (aliased)
__device__ float g_h [(size_t)N_NODES * NCLASS];
__device__ __align__(16) float g_vA[(size_t)N_NODES * NCLASS];  // fp16 iterate ping
__device__ __align__(16) float g_vB[(size_t)N_NODES * NCLASS];  // fp16 iterate pong
__device__ float g_dinv[N_NODES];
__device__ int   g_cnt [N_NODES];
__device__ int   g_fill[N_NODES];
__device__ int   g_rowstart[N_NODES + 1];
__device__ int   g_cols[N_EDGES];
__device__ int   g_bsum[128];
// fp16 weights (single-term quantized)
__device__ __align__(16) __half g_w1h[NHID * NFEAT];
__device__ __align__(16) __half g_w2h[NHID * NHID];
__device__ __align__(16) __half g_w3h[NCLASS * NHID];

// ---------------- helpers ----------------
__device__ __forceinline__ uint32_t smem_u32(const void* p) {
    uint32_t a;
    asm("{ .reg .u64 t; cvta.to.shared.u64 t, %1; cvt.u32.u64 %0, t; }" : "=r"(a) : "l"(p));
    return a;
}

__device__ __forceinline__ void mma16816h(float c[4], const uint32_t a[4],
                                          uint32_t b0, uint32_t b1) {
    asm volatile(
        "mma.sync.aligned.m16n8k16.row.col.f32.f16.f16.f32 "
        "{%0,%1,%2,%3}, {%4,%5,%6,%7}, {%8,%9}, {%0,%1,%2,%3};"
        : "+f"(c[0]), "+f"(c[1]), "+f"(c[2]), "+f"(c[3])
        : "r"(a[0]), "r"(a[1]), "r"(a[2]), "r"(a[3]), "r"(b0), "r"(b1));
}

#define LDSM_X4(r0, r1, r2, r3, addr) \
    asm volatile("ldmatrix.sync.aligned.m8n8.x4.shared.b16 {%0,%1,%2,%3}, [%4];" \
                 : "=r"(r0), "=r"(r1), "=r"(r2), "=r"(r3) : "r"(addr))

__device__ __forceinline__ void cp16(uint32_t dst, const void* src, uint32_t bytes) {
    asm volatile("cp.async.cg.shared.global [%0], [%1], 16, %2;"
                 :: "r"(dst), "l"(src), "r"(bytes));
}
#define CP_COMMIT() asm volatile("cp.async.commit_group;" ::: "memory")
#define CP_WAIT(n)  asm volatile("cp.async.wait_group %0;" :: "n"(n) : "memory")

// fp32x4 -> fp16 hi (uint2) + fp16 lo (uint2)
__device__ __forceinline__ void split4h(float4 v, uint2& hi, uint2& lo) {
    __half hx = __float2half_rn(v.x);
    __half hy = __float2half_rn(v.y);
    __half hz = __float2half_rn(v.z);
    __half hw = __float2half_rn(v.w);
    __half lx = __float2half_rn(v.x - __half2float(hx));
    __half ly = __float2half_rn(v.y - __half2float(hy));
    __half lz = __float2half_rn(v.z - __half2float(hz));
    __half lw = __float2half_rn(v.w - __half2float(hw));
    hi.x = ((uint32_t)__half_as_ushort(hy) << 16) | __half_as_ushort(hx);
    hi.y = ((uint32_t)__half_as_ushort(hw) << 16) | __half_as_ushort(hz);
    lo.x = ((uint32_t)__half_as_ushort(ly) << 16) | __half_as_ushort(lx);
    lo.y = ((uint32_t)__half_as_ushort(lw) << 16) | __half_as_ushort(lz);
}

// fp32x4 -> fp16 hi only
__device__ __forceinline__ uint2 pack4h(float4 v) {
    __half2 a = __floats2half2_rn(v.x, v.y);
    __half2 b = __floats2half2_rn(v.z, v.w);
    uint2 r;
    r.x = *(uint32_t*)&a;
    r.y = *(uint32_t*)&b;
    return r;
}

__device__ __forceinline__ void split2h(float2 v, uint32_t& hi, uint32_t& lo) {
    __half hx = __float2half_rn(v.x);
    __half hy = __float2half_rn(v.y);
    __half lx = __float2half_rn(v.x - __half2float(hx));
    __half ly = __float2half_rn(v.y - __half2float(hy));
    hi = ((uint32_t)__half_as_ushort(hy) << 16) | __half_as_ushort(hx);
    lo = ((uint32_t)__half_as_ushort(ly) << 16) | __half_as_ushort(lx);
}

// unpack a uint4 (8 fp16) and accumulate into 8 floats
__device__ __forceinline__ void acc8(float a[8], uint4 p) {
    float2 q;
    q = __half22float2(*(__half2*)&p.x); a[0] += q.x; a[1] += q.y;
    q = __half22float2(*(__half2*)&p.y); a[2] += q.x; a[3] += q.y;
    q = __half22float2(*(__half2*)&p.z); a[4] += q.x; a[5] += q.y;
    q = __half22float2(*(__half2*)&p.w); a[6] += q.x; a[7] += q.y;
}

// ---------------- graph preprocessing ----------------
__global__ void zero_counts() {
    int i = blockIdx.x * blockDim.x + threadIdx.x;
    if (i < N_NODES) { g_cnt[i] = 0; g_fill[i] = 0; }
}
__global__ void count_deg(const int* __restrict__ rows) {
    int e = blockIdx.x * blockDim.x + threadIdx.x;
    if (e < N_EDGES) atomicAdd(&g_cnt[rows[e]], 1);
}
__global__ void compute_dinv() {
    int i = blockIdx.x * blockDim.x + threadIdx.x;
    if (i < N_NODES) g_dinv[i] = 1.0f / (float)(g_cnt[i] + 1);
}
__global__ void scan_blocks() {
    __shared__ int s[SCAN_T];
    int t   = threadIdx.x;
    int gid = blockIdx.x * SCAN_T + t;
    int v   = (gid < N_NODES) ? g_cnt[gid] : 0;
    s[t] = v;
    __syncthreads();
    #pragma unroll
    for (int off = 1; off < SCAN_T; off <<= 1) {
        int x = (t >= off) ? s[t - off] : 0;
        __syncthreads();
        s[t] += x;
        __syncthreads();
    }
    if (gid < N_NODES) g_rowstart[gid] = s[t] - v;
    if (t == SCAN_T - 1) g_bsum[blockIdx.x] = s[t];
}
__global__ void scan_offsets() {
    if (threadIdx.x == 0 && blockIdx.x == 0) {
        int acc = 0;
        for (int i = 0; i < NBLK; i++) { int t = g_bsum[i]; g_bsum[i] = acc; acc += t; }
        g_rowstart[N_NODES] = acc;
    }
}
__global__ void scan_add() {
    int t   = threadIdx.x;
    int gid = blockIdx.x * SCAN_T + t;
    if (gid < N_NODES) g_rowstart[gid] += g_bsum[blockIdx.x];
}
__global__ void scatter_edges(const int* __restrict__ rows, const int* __restrict__ cols) {
    int e = blockIdx.x * blockDim.x + threadIdx.x;
    if (e < N_EDGES) {
        int r   = rows[e];
        int pos = g_rowstart[r] + atomicAdd(&g_fill[r], 1);
        g_cols[pos] = cols[e];
    }
}
__global__ void conv_w(const float* __restrict__ src, __half* __restrict__ dst, int n) {
    int i = blockIdx.x * 256 + threadIdx.x;
    if (i < n) dst[i] = __float2half_rn(src[i]);
}

// ====== HMMA GEMM, fp16 split, K-tile 32, 2-stage cp.async pipeline ======
// ATERMS: 1 = A single fp16 term; 2 = A exact (hi+lo)
// OUTMODE: 0 = fp32 C; 1 = fp16 hi/lo; 2 = fp32 C + fp16 v0; 3 = fp16 single only
#define RSB 80             // smem row stride bytes (64B data + 16B pad)

template<int BN, int RELU, int AHL, int OUTMODE, int ATERMS>
__global__ __launch_bounds__(256, 2)
void gemm_hmma(const float* __restrict__ Af,
               const __half* __restrict__ Ahi_g,
               const __half* __restrict__ Alo_g,
               const __half* __restrict__ Wh_g,
               const float* __restrict__ bias,
               float* __restrict__ C,
               __half* __restrict__ Chi,
               __half* __restrict__ Clo,
               __half* __restrict__ Chalf,
               int Nrows, int Mcols, int K)
{
    constexpr int NJ      = BN / 16;
    constexpr int ABYTES  = 128 * RSB;                   // 10240
    constexpr int BBYTES  = BN * RSB;
    constexpr int STAGE   = ATERMS * ABYTES + BBYTES;    // AHI[|ALO]|BH
    constexpr int OFF_BS  = 2 * STAGE;
    constexpr int BCHUNKS = BN / 64;                     // cp.async 16B iters for B

    extern __shared__ __align__(16) char sm[];

    const uint32_t smb = smem_u32(sm);
    const int tid = threadIdx.x;
    const int wid = tid >> 5;
    const int lid = tid & 31;
    const int warpM = (wid & 3) * 32;
    const int warpN = (wid >> 2) * (BN / 2);
    const int rowBase = blockIdx.y * 128;
    const int colBase = blockIdx.x * BN;
    const int NT = K / 32;

    // bias -> smem
    for (int i = tid; i < BN; i += 256) {
        int gc = colBase + i;
        *(float*)(sm + OFF_BS + i * 4) = (gc < Mcols) ? bias[gc] : 0.0f;
    }

    // per-lane ldmatrix address components
    const int aRow  = (lid & 7) + ((lid >> 3) & 1) * 8;
    const int aColB = (lid >> 4) * 16;
    const int bN    = ((lid >> 4) * 8) + (lid & 7);
    const int bColB = ((lid >> 3) & 1) * 16;

    const uint32_t aAddr0 = smb + (warpM + aRow) * RSB + aColB;
    const uint32_t bAddr0 = smb + ATERMS * ABYTES + (warpN + bN) * RSB + bColB;

    float acc[2][NJ][4];
    #pragma unroll
    for (int i = 0; i < 2; i++)
        #pragma unroll
        for (int j = 0; j < NJ; j++)
            #pragma unroll
            for (int q = 0; q < 4; q++) acc[i][j][q] = 0.0f;

    float4 paf[4];   // fp32-A prefetch (AHL=0 only)

    // cp.async A (pre-quantized fp16 path)
    auto cpA = [&](int t, int st) {
        const int kt = t * 32;
        char* base = sm + st * STAGE;
        #pragma unroll
        for (int i = 0; i < 2; i++) {
            int idx = tid + i * 256;
            int row = idx >> 2;
            int c   = idx & 3;
            int gr  = rowBase + row;
            uint32_t sz = (gr < Nrows) ? 16u : 0u;
            int gra = (gr < Nrows) ? gr : 0;
            uint32_t so = smem_u32(base + row * RSB + c * 16);
            cp16(so, Ahi_g + (size_t)gra * K + kt + c * 8, sz);
            if (ATERMS == 2)
                cp16(so + ABYTES, Alo_g + (size_t)gra * K + kt + c * 8, sz);
        }
    };
    // cp.async B: BN x 32 fp16
    auto cpB = [&](int t, int st) {
        const int kt = t * 32;
        char* base = sm + st * STAGE + ATERMS * ABYTES;
        #pragma unroll
        for (int i = 0; i < BCHUNKS; i++) {
            int idx = tid + i * 256;
            int row = idx >> 2;
            int c   = idx & 3;
            int gm  = colBase + row;
            uint32_t sz = (gm < Mcols) ? 16u : 0u;
            int gma = (gm < Mcols) ? gm : 0;
            uint32_t so = smem_u32(base + row * RSB + c * 16);
            cp16(so, Wh_g + (size_t)gma * K + kt + c * 8, sz);
        }
    };
    // fp32 A prefetch to regs (AHL=0): 128x32 fp32, 4 float4/thread
    auto ldA = [&](int t) {
        const int kt = t * 32;
        #pragma unroll
        for (int i = 0; i < 4; i++) {
            int idx = tid + i * 256;
            int row = idx >> 3;
            int c4  = idx & 7;
            int gr  = rowBase + row;
            paf[i] = make_float4(0.f, 0.f, 0.f, 0.f);
            if (gr < Nrows) paf[i] = *(const float4*)(Af + (size_t)gr * K + kt + c4 * 4);
        }
    };
    auto stsA = [&](int st) {
        char* base = sm + st * STAGE;
        #pragma unroll
        for (int i = 0; i < 4; i++) {
            int idx = tid + i * 256;
            int row = idx >> 3;
            int c4  = idx & 7;
            if (ATERMS == 2) {
                uint2 hi, lo; split4h(paf[i], hi, lo);
                *(uint2*)(base + row * RSB + c4 * 8) = hi;
                *(uint2*)(base + ABYTES + row * RSB + c4 * 8) = lo;
            } else {
                *(uint2*)(base + row * RSB + c4 * 8) = pack4h(paf[i]);
            }
        }
    };

    auto MMA = [&](int st) {
        const uint32_t aA = aAddr0 + st * STAGE;
        const uint32_t bA = bAddr0 + st * STAGE;
        #pragma unroll
        for (int ks = 0; ks < 2; ks++) {
            const uint32_t kOff = ks * 32;
            uint32_t ah[2][4], al[2][4];
            #pragma unroll
            for (int i = 0; i < 2; i++) {
                uint32_t aa = aA + i * 16 * RSB + kOff;
                LDSM_X4(ah[i][0], ah[i][1], ah[i][2], ah[i][3], aa);
                if (ATERMS == 2)
                    LDSM_X4(al[i][0], al[i][1], al[i][2], al[i][3], aa + ABYTES);
            }
            #pragma unroll
            for (int jp = 0; jp < NJ / 2; jp++) {
                uint32_t bb = bA + jp * 16 * RSB + kOff;
                uint32_t bh0, bh1, bh2, bh3;
                LDSM_X4(bh0, bh1, bh2, bh3, bb);
                #pragma unroll
                for (int i = 0; i < 2; i++) {
                    mma16816h(acc[i][2 * jp],     ah[i], bh0, bh1);
                    mma16816h(acc[i][2 * jp + 1], ah[i], bh2, bh3);
                    if (ATERMS == 2) {
                        mma16816h(acc[i][2 * jp],     al[i], bh0, bh1);
                        mma16816h(acc[i][2 * jp + 1], al[i], bh2, bh3);
                    }
                }
            }
        }
    };

    // ---- prologue ----
    if (AHL) cpA(0, 0); else ldA(0);
    cpB(0, 0);
    CP_COMMIT();

    // ---- mainloop ----
    for (int t = 0; t < NT; t++) {
        const int st = t & 1;
        if (!AHL) stsA(st);
        if (t + 1 < NT) {
            const int sn = (t + 1) & 1;
            if (AHL) cpA(t + 1, sn); else ldA(t + 1);
            cpB(t + 1, sn);
        }
        CP_COMMIT();
        if (t + 1 < NT) { CP_WAIT(1); } else { CP_WAIT(0); }
        __syncthreads();
        MMA(st);
        __syncthreads();
    }

    // ---- epilogue ----
    const int rBase = rowBase + warpM + (lid >> 2);
    const int cOff  = warpN + (lid & 3) * 2;
    #pragma unroll
    for (int i = 0; i < 2; i++) {
        #pragma unroll
        for (int j = 0; j < NJ; j++) {
            int cl = cOff + j * 8;
            int gc = colBase + cl;
            if (gc >= Mcols) continue;
            float2 bb = *(const float2*)(sm + OFF_BS + cl * 4);
            int r0 = rBase + i * 16;
            int r1 = r0 + 8;
            float2 v0, v1;
            v0.x = acc[i][j][0] + bb.x; v0.y = acc[i][j][1] + bb.y;
            v1.x = acc[i][j][2] + bb.x; v1.y = acc[i][j][3] + bb.y;
            if (RELU) {
                v0.x = fmaxf(v0.x, 0.f); v0.y = fmaxf(v0.y, 0.f);
                v1.x = fmaxf(v1.x, 0.f); v1.y = fmaxf(v1.y, 0.f);
            }
            if (OUTMODE == 1) {
                uint32_t h0, l0, h1v, l1;
                split2h(v0, h0, l0);
                split2h(v1, h1v, l1);
                if (r0 < Nrows) {
                    *(uint32_t*)(Chi + (size_t)r0 * Mcols + gc) = h0;
                    *(uint32_t*)(Clo + (size_t)r0 * Mcols + gc) = l0;
                }
                if (r1 < Nrows) {
                    *(uint32_t*)(Chi + (size_t)r1 * Mcols + gc) = h1v;
                    *(uint32_t*)(Clo + (size_t)r1 * Mcols + gc) = l1;
                }
            } else if (OUTMODE == 3) {
                __half2 q0 = __floats2half2_rn(v0.x, v0.y);
                __half2 q1 = __floats2half2_rn(v1.x, v1.y);
                if (r0 < Nrows) *(uint32_t*)(Chalf + (size_t)r0 * Mcols + gc) = *(uint32_t*)&q0;
                if (r1 < Nrows) *(uint32_t*)(Chalf + (size_t)r1 * Mcols + gc) = *(uint32_t*)&q1;
            } else {
                if (r0 < Nrows) *(float2*)(C + (size_t)r0 * Mcols + gc) = v0;
                if (r1 < Nrows) *(float2*)(C + (size_t)r1 * Mcols + gc) = v1;
                if (OUTMODE == 2) {
                    __half2 q0 = __floats2half2_rn(v0.x, v0.y);
                    __half2 q1 = __floats2half2_rn(v1.x, v1.y);
                    if (r0 < Nrows) *(uint32_t*)(Chalf + (size_t)r0 * Mcols + gc) = *(uint32_t*)&q0;
                    if (r1 < Nrows) *(uint32_t*)(Chalf + (size_t)r1 * Mcols + gc) = *(uint32_t*)&q1;
                }
            }
        }
    }
}

// ---------------- SpMM power-iteration step, fp16 iterate ----------------
#define SPH_T 320

template<int FINAL>
__global__ __launch_bounds__(SPH_T)
void spmm_h(const uint4* __restrict__ vh,     // fp16 iterate: 5 uint4 per row
            const float4* __restrict__ hf,    // fp32 h: 10 float4 per row
            uint4* __restrict__ dsth,         // fp16 out (FINAL=0)
            float4* __restrict__ dstf)        // fp32 out (FINAL=1)
{
    int t = blockIdx.x * SPH_T + threadIdx.x;
    int r = t / 5;
    int f = t - r * 5;
    if (r >= N_NODES) return;

    const int s = g_rowstart[r];
    const int e = g_rowstart[r + 1];

    float a[8];
    #pragma unroll
    for (int j = 0; j < 8; j++) a[j] = 0.0f;

    int i = s;
    for (; i + 4 <= e; i += 4) {
        int c0 = g_cols[i + 0], c1 = g_cols[i + 1];
        int c2 = g_cols[i + 2], c3 = g_cols[i + 3];
        uint4 p0 = __ldg(vh + (size_t)c0 * 5 + f);
        uint4 p1 = __ldg(vh + (size_t)c1 * 5 + f);
        uint4 p2 = __ldg(vh + (size_t)c2 * 5 + f);
        uint4 p3 = __ldg(vh + (size_t)c3 * 5 + f);
        acc8(a, p0); acc8(a, p1); acc8(a, p2); acc8(a, p3);
    }
    for (; i < e; i++) {
        uint4 p = __ldg(vh + (size_t)g_cols[i] * 5 + f);
        acc8(a, p);
    }

    // self-loop term
    {
        uint4 p = __ldg(vh + (size_t)r * 5 + f);
        acc8(a, p);
    }

    const float w = 0.5f * g_dinv[r];
    float4 h0 = __ldg(hf + (size_t)r * 10 + f * 2);
    float4 h1 = __ldg(hf + (size_t)r * 10 + f * 2 + 1);

    float o[8];
    o[0] = w * a[0] + 0.5f * h0.x;
    o[1] = w * a[1] + 0.5f * h0.y;
    o[2] = w * a[2] + 0.5f * h0.z;
    o[3] = w * a[3] + 0.5f * h0.w;
    o[4] = w * a[4] + 0.5f * h1.x;
    o[5] = w * a[5] + 0.5f * h1.y;
    o[6] = w * a[6] + 0.5f * h1.z;
    o[7] = w * a[7] + 0.5f * h1.w;

    if (FINAL) {
        dstf[(size_t)r * 10 + f * 2]     = make_float4(o[0], o[1], o[2], o[3]);
        dstf[(size_t)r * 10 + f * 2 + 1] = make_float4(o[4], o[5], o[6], o[7]);
    } else {
        __half2 q0 = __floats2half2_rn(o[0], o[1]);
        __half2 q1 = __floats2half2_rn(o[2], o[3]);
        __half2 q2 = __floats2half2_rn(o[4], o[5]);
        __half2 q3 = __floats2half2_rn(o[6], o[7]);
        uint4 pk;
        pk.x = *(uint32_t*)&q0; pk.y = *(uint32_t*)&q1;
        pk.z = *(uint32_t*)&q2; pk.w = *(uint32_t*)&q3;
        dsth[(size_t)r * 5 + f] = pk;
    }
}

// ---------------- host ----------------
extern "C" void kernel_launch(void* const* d_in, const int* in_sizes, int n_in,
                              void* d_out, int out_size)
{
    const float* x  = (const float*)d_in[0];
    const int*   ei = (const int*)  d_in[1];
    const float* W1 = (const float*)d_in[2];
    const float* b1 = (const float*)d_in[3];
    const float* W2 = (const float*)d_in[4];
    const float* b2 = (const float*)d_in[5];
    const float* W3 = (const float*)d_in[6];
    const float* b3 = (const float*)d_in[7];
    float* out = (float*)d_out;

    const int* rows = ei;
    const int* cols = ei + N_EDGES;

    void *p;
    float *h1, *h2, *h, *vA, *vB;
    __half *w1h, *w2h, *w3h;
    cudaGetSymbolAddress(&p, g_h1);  h1 = (float*)p;
    cudaGetSymbolAddress(&p, g_h2);  h2 = (float*)p;
    cudaGetSymbolAddress(&p, g_h);   h  = (float*)p;
    cudaGetSymbolAddress(&p, g_vA);  vA = (float*)p;
    cudaGetSymbolAddress(&p, g_vB);  vB = (float*)p;
    cudaGetSymbolAddress(&p, g_w1h); w1h = (__half*)p;
    cudaGetSymbolAddress(&p, g_w2h); w2h = (__half*)p;
    cudaGetSymbolAddress(&p, g_w3h); w3h = (__half*)p;

    __half* h1h  = (__half*)h1;                      // single-term fp16 h1
    __half* h2hi = (__half*)h2;
    __half* h2lo = h2hi + (size_t)N_NODES * NHID;

    // side stream + events for CSR/W-conv overlap
    cudaStream_t s1;
    cudaStreamCreateWithFlags(&s1, cudaStreamNonBlocking);
    cudaEvent_t evFork, evJoin, evW;
    cudaEventCreateWithFlags(&evFork, cudaEventDisableTiming);
    cudaEventCreateWithFlags(&evJoin, cudaEventDisableTiming);
    cudaEventCreateWithFlags(&evW, cudaEventDisableTiming);

    // ---- fork: w2/w3 conv + CSR build on side stream ----
    cudaEventRecord(evFork, 0);
    cudaStreamWaitEvent(s1, evFork, 0);
    conv_w<<<(NHID * NHID   + 255) / 256, 256, 0, s1>>>(W2, w2h, NHID * NHID);
    conv_w<<<(NCLASS * NHID + 255) / 256, 256, 0, s1>>>(W3, w3h, NCLASS * NHID);
    cudaEventRecord(evW, s1);
    zero_counts  <<<(N_NODES + 255) / 256, 256, 0, s1>>>();
    count_deg    <<<(N_EDGES + 255) / 256, 256, 0, s1>>>(rows);
    compute_dinv <<<(N_NODES + 255) / 256, 256, 0, s1>>>();
    scan_blocks  <<<NBLK, SCAN_T, 0, s1>>>();
    scan_offsets <<<1, 32, 0, s1>>>();
    scan_add     <<<NBLK, SCAN_T, 0, s1>>>();
    scatter_edges<<<(N_EDGES + 255) / 256, 256, 0, s1>>>(rows, cols);
    cudaEventRecord(evJoin, s1);

    // ---- main stream: w1 conv + GEMM chain ----
    conv_w<<<(NHID * NFEAT + 255) / 256, 256>>>(W1, w1h, NHID * NFEAT);

    const int STG1   = 128 * RSB + 128 * RSB;            // 20480 (ATERMS=1, BN=128)
    const int STG64  = 2 * (128 * RSB) + 64 * RSB;       // 25600 (ATERMS=2, BN=64)
    const int SMEM_1   = 2 * STG1 + 128 * 4;             // 41472
    const int SMEM_64  = 2 * STG64 + 64 * 4;             // 51456
    cudaFuncSetAttribute((const void*)gemm_hmma<128, 1, 0, 3, 1>,
                         cudaFuncAttributeMaxDynamicSharedMemorySize, SMEM_1);
    cudaFuncSetAttribute((const void*)gemm_hmma<128, 1, 1, 1, 1>,
                         cudaFuncAttributeMaxDynamicSharedMemorySize, SMEM_1);
    cudaFuncSetAttribute((const void*)gemm_hmma<64, 0, 1, 2, 2>,
                         cudaFuncAttributeMaxDynamicSharedMemorySize, SMEM_64);

    const int MG = (N_NODES + 127) / 128;   // 782
    // GEMM1: A = fp16(x) single term; OUT = single fp16 h1
    gemm_hmma<128, 1, 0, 3, 1><<<dim3(2, MG), 256, SMEM_1>>>(
        x, nullptr, nullptr, w1h, b1, nullptr, nullptr, nullptr, h1h,
        N_NODES, NHID, NFEAT);

    // GEMM2: A = fp16 h1 single term; OUT = fp16 hi/lo h2 (exact for GEMM3)
    cudaStreamWaitEvent(0, evW, 0);
    gemm_hmma<128, 1, 1, 1, 1><<<dim3(2, MG), 256, SMEM_1>>>(
        nullptr, h1h, nullptr, w2h, b2, nullptr, h2hi, h2lo, nullptr,
        N_NODES, NHID, NHID);
    // GEMM3: A exact 2-term; emits fp32 h AND fp16 v0 (fused)
    gemm_hmma<64, 0, 1, 2, 2><<<dim3(1, MG), 256, SMEM_64>>>(
        nullptr, h2hi, h2lo, w3h, b3, h, nullptr, nullptr, (__half*)vA,
        N_NODES, NCLASS, NHID);

    // ---- join: CSR must be done before propagation ----
    cudaStreamWaitEvent(0, evJoin, 0);

    // ---- 10 power iterations (fp16 iterate, fp32 h-term and final) ----
    const int SP_G = (N_NODES * 5 + SPH_T - 1) / SPH_T;   // 1563
    const uint4* src = (const uint4*)vA;
    for (int it = 0; it < 9; it++) {
        uint4* dst = (uint4*)((it & 1) ? vA : vB);
        spmm_h<0><<<SP_G, SPH_T>>>(src, (const float4*)h, dst, nullptr);
        src = dst;
    }
    spmm_h<1><<<SP_G, SPH_T>>>(src, (const float4*)h, nullptr, (float4*)out);
}

// round 17
// speedup vs baseline: 1.7182x; 1.0552x over previous
#include <cuda_runtime.h>
#include <cuda_bf16.h>
#include <cuda_fp16.h>
#include <cstdint>

#define N_NODES 100000
#define N_EDGES 1600000
#define NFEAT   512
#define NHID    256
#define NCLASS  40

#define SCAN_T  1024
#define NBLK    ((N_NODES + SCAN_T - 1) / SCAN_T)   // 98

// ---------------- scratch (static device globals; no allocation) ----------------
__device__ float g_h1[(size_t)N_NODES * NHID];   // holds fp16 h1 (single term, aliased)
__device__ float g_h2[(size_t)N_NODES * NHID];   // holds fp16 h2 (single term, aliased)
__device__ float g_h [(size_t)N_NODES * NCLASS]; // fp32 h (final-iteration term)
__device__ __align__(16) float g_vA[(size_t)N_NODES * NCLASS];  // fp16 iterate ping
__device__ __align__(16) float g_vB[(size_t)N_NODES * NCLASS];  // fp16 iterate pong
__device__ __align__(16) __half g_hh[(size_t)N_NODES * NCLASS]; // fp16 h (iter term)
__device__ float g_dinv[N_NODES];
__device__ int   g_cnt [N_NODES];
__device__ int   g_fill[N_NODES];
__device__ int   g_rowstart[N_NODES + 1];
__device__ int   g_cols[N_EDGES];
__device__ int   g_bsum[128];
// fp16 weights (single-term quantized)
__device__ __align__(16) __half g_w1h[NHID * NFEAT];
__device__ __align__(16) __half g_w2h[NHID * NHID];
__device__ __align__(16) __half g_w3h[NCLASS * NHID];

// ---------------- helpers ----------------
__device__ __forceinline__ uint32_t smem_u32(const void* p) {
    uint32_t a;
    asm("{ .reg .u64 t; cvta.to.shared.u64 t, %1; cvt.u32.u64 %0, t; }" : "=r"(a) : "l"(p));
    return a;
}

__device__ __forceinline__ void mma16816h(float c[4], const uint32_t a[4],
                                          uint32_t b0, uint32_t b1) {
    asm volatile(
        "mma.sync.aligned.m16n8k16.row.col.f32.f16.f16.f32 "
        "{%0,%1,%2,%3}, {%4,%5,%6,%7}, {%8,%9}, {%0,%1,%2,%3};"
        : "+f"(c[0]), "+f"(c[1]), "+f"(c[2]), "+f"(c[3])
        : "r"(a[0]), "r"(a[1]), "r"(a[2]), "r"(a[3]), "r"(b0), "r"(b1));
}

#define LDSM_X4(r0, r1, r2, r3, addr) \
    asm volatile("ldmatrix.sync.aligned.m8n8.x4.shared.b16 {%0,%1,%2,%3}, [%4];" \
                 : "=r"(r0), "=r"(r1), "=r"(r2), "=r"(r3) : "r"(addr))

__device__ __forceinline__ void cp16(uint32_t dst, const void* src, uint32_t bytes) {
    asm volatile("cp.async.cg.shared.global [%0], [%1], 16, %2;"
                 :: "r"(dst), "l"(src), "r"(bytes));
}
#define CP_COMMIT() asm volatile("cp.async.commit_group;" ::: "memory")
#define CP_WAIT(n)  asm volatile("cp.async.wait_group %0;" :: "n"(n) : "memory")

// fp32x4 -> fp16 hi (uint2) + fp16 lo (uint2)
__device__ __forceinline__ void split4h(float4 v, uint2& hi, uint2& lo) {
    __half hx = __float2half_rn(v.x);
    __half hy = __float2half_rn(v.y);
    __half hz = __float2half_rn(v.z);
    __half hw = __float2half_rn(v.w);
    __half lx = __float2half_rn(v.x - __half2float(hx));
    __half ly = __float2half_rn(v.y - __half2float(hy));
    __half lz = __float2half_rn(v.z - __half2float(hz));
    __half lw = __float2half_rn(v.w - __half2float(hw));
    hi.x = ((uint32_t)__half_as_ushort(hy) << 16) | __half_as_ushort(hx);
    hi.y = ((uint32_t)__half_as_ushort(hw) << 16) | __half_as_ushort(hz);
    lo.x = ((uint32_t)__half_as_ushort(ly) << 16) | __half_as_ushort(lx);
    lo.y = ((uint32_t)__half_as_ushort(lw) << 16) | __half_as_ushort(lz);
}

// fp32x4 -> fp16 hi only
__device__ __forceinline__ uint2 pack4h(float4 v) {
    __half2 a = __floats2half2_rn(v.x, v.y);
    __half2 b = __floats2half2_rn(v.z, v.w);
    uint2 r;
    r.x = *(uint32_t*)&a;
    r.y = *(uint32_t*)&b;
    return r;
}

// unpack a uint4 (8 fp16) and accumulate into 8 floats
__device__ __forceinline__ void acc8(float a[8], uint4 p) {
    float2 q;
    q = __half22float2(*(__half2*)&p.x); a[0] += q.x; a[1] += q.y;
    q = __half22float2(*(__half2*)&p.y); a[2] += q.x; a[3] += q.y;
    q = __half22float2(*(__half2*)&p.z); a[4] += q.x; a[5] += q.y;
    q = __half22float2(*(__half2*)&p.w); a[6] += q.x; a[7] += q.y;
}

// ---------------- graph preprocessing ----------------
__global__ void zero_counts() {
    int i = blockIdx.x * blockDim.x + threadIdx.x;
    if (i < N_NODES) { g_cnt[i] = 0; g_fill[i] = 0; }
}
__global__ void count_deg(const int* __restrict__ rows) {
    int e = blockIdx.x * blockDim.x + threadIdx.x;
    if (e < N_EDGES) atomicAdd(&g_cnt[rows[e]], 1);
}
__global__ void compute_dinv() {
    int i = blockIdx.x * blockDim.x + threadIdx.x;
    if (i < N_NODES) g_dinv[i] = 1.0f / (float)(g_cnt[i] + 1);
}
__global__ void scan_blocks() {
    __shared__ int s[SCAN_T];
    int t   = threadIdx.x;
    int gid = blockIdx.x * SCAN_T + t;
    int v   = (gid < N_NODES) ? g_cnt[gid] : 0;
    s[t] = v;
    __syncthreads();
    #pragma unroll
    for (int off = 1; off < SCAN_T; off <<= 1) {
        int x = (t >= off) ? s[t - off] : 0;
        __syncthreads();
        s[t] += x;
        __syncthreads();
    }
    if (gid < N_NODES) g_rowstart[gid] = s[t] - v;
    if (t == SCAN_T - 1) g_bsum[blockIdx.x] = s[t];
}
__global__ void scan_offsets() {
    if (threadIdx.x == 0 && blockIdx.x == 0) {
        int acc = 0;
        for (int i = 0; i < NBLK; i++) { int t = g_bsum[i]; g_bsum[i] = acc; acc += t; }
        g_rowstart[N_NODES] = acc;
    }
}
__global__ void scan_add() {
    int t   = threadIdx.x;
    int gid = blockIdx.x * SCAN_T + t;
    if (gid < N_NODES) g_rowstart[gid] += g_bsum[blockIdx.x];
}
__global__ void scatter_edges(const int* __restrict__ rows, const int* __restrict__ cols) {
    int e = blockIdx.x * blockDim.x + threadIdx.x;
    if (e < N_EDGES) {
        int r   = rows[e];
        int pos = g_rowstart[r] + atomicAdd(&g_fill[r], 1);
        g_cols[pos] = cols[e];
    }
}
__global__ void conv_w(const float* __restrict__ src, __half* __restrict__ dst, int n) {
    int i = blockIdx.x * 256 + threadIdx.x;
    if (i < n) dst[i] = __float2half_rn(src[i]);
}

// ====== HMMA GEMM, fp16 single/double-term A, K-tile 32, 2-stage cp.async ======
// ATERMS: 1 = A single fp16 term; 2 = A exact (hi+lo)
// OUTMODE: 3 = fp16 single only; 4 = fp32 C + fp16 to Chalf AND Chalf2
#define RSB 80             // smem row stride bytes (64B data + 16B pad)

template<int BN, int RELU, int AHL, int OUTMODE, int ATERMS>
__global__ __launch_bounds__(256, 2)
void gemm_hmma(const float* __restrict__ Af,
               const __half* __restrict__ Ahi_g,
               const __half* __restrict__ Alo_g,
               const __half* __restrict__ Wh_g,
               const float* __restrict__ bias,
               float* __restrict__ C,
               __half* __restrict__ Chalf,
               __half* __restrict__ Chalf2,
               int Nrows, int Mcols, int K)
{
    constexpr int NJ      = BN / 16;
    constexpr int ABYTES  = 128 * RSB;                   // 10240
    constexpr int BBYTES  = BN * RSB;
    constexpr int STAGE   = ATERMS * ABYTES + BBYTES;
    constexpr int OFF_BS  = 2 * STAGE;
    constexpr int BCHUNKS = BN / 64;

    extern __shared__ __align__(16) char sm[];

    const uint32_t smb = smem_u32(sm);
    const int tid = threadIdx.x;
    const int wid = tid >> 5;
    const int lid = tid & 31;
    const int warpM = (wid & 3) * 32;
    const int warpN = (wid >> 2) * (BN / 2);
    const int rowBase = blockIdx.y * 128;
    const int colBase = blockIdx.x * BN;
    const int NT = K / 32;

    // bias -> smem
    for (int i = tid; i < BN; i += 256) {
        int gc = colBase + i;
        *(float*)(sm + OFF_BS + i * 4) = (gc < Mcols) ? bias[gc] : 0.0f;
    }

    // per-lane ldmatrix address components
    const int aRow  = (lid & 7) + ((lid >> 3) & 1) * 8;
    const int aColB = (lid >> 4) * 16;
    const int bN    = ((lid >> 4) * 8) + (lid & 7);
    const int bColB = ((lid >> 3) & 1) * 16;

    const uint32_t aAddr0 = smb + (warpM + aRow) * RSB + aColB;
    const uint32_t bAddr0 = smb + ATERMS * ABYTES + (warpN + bN) * RSB + bColB;

    float acc[2][NJ][4];
    #pragma unroll
    for (int i = 0; i < 2; i++)
        #pragma unroll
        for (int j = 0; j < NJ; j++)
            #pragma unroll
            for (int q = 0; q < 4; q++) acc[i][j][q] = 0.0f;

    float4 paf[4];   // fp32-A prefetch (AHL=0 only)

    auto cpA = [&](int t, int st) {
        const int kt = t * 32;
        char* base = sm + st * STAGE;
        #pragma unroll
        for (int i = 0; i < 2; i++) {
            int idx = tid + i * 256;
            int row = idx >> 2;
            int c   = idx & 3;
            int gr  = rowBase + row;
            uint32_t sz = (gr < Nrows) ? 16u : 0u;
            int gra = (gr < Nrows) ? gr : 0;
            uint32_t so = smem_u32(base + row * RSB + c * 16);
            cp16(so, Ahi_g + (size_t)gra * K + kt + c * 8, sz);
            if (ATERMS == 2)
                cp16(so + ABYTES, Alo_g + (size_t)gra * K + kt + c * 8, sz);
        }
    };
    auto cpB = [&](int t, int st) {
        const int kt = t * 32;
        char* base = sm + st * STAGE + ATERMS * ABYTES;
        #pragma unroll
        for (int i = 0; i < BCHUNKS; i++) {
            int idx = tid + i * 256;
            int row = idx >> 2;
            int c   = idx & 3;
            int gm  = colBase + row;
            uint32_t sz = (gm < Mcols) ? 16u : 0u;
            int gma = (gm < Mcols) ? gm : 0;
            uint32_t so = smem_u32(base + row * RSB + c * 16);
            cp16(so, Wh_g + (size_t)gma * K + kt + c * 8, sz);
        }
    };
    auto ldA = [&](int t) {
        const int kt = t * 32;
        #pragma unroll
        for (int i = 0; i < 4; i++) {
            int idx = tid + i * 256;
            int row = idx >> 3;
            int c4  = idx & 7;
            int gr  = rowBase + row;
            paf[i] = make_float4(0.f, 0.f, 0.f, 0.f);
            if (gr < Nrows) paf[i] = *(const float4*)(Af + (size_t)gr * K + kt + c4 * 4);
        }
    };
    auto stsA = [&](int st) {
        char* base = sm + st * STAGE;
        #pragma unroll
        for (int i = 0; i < 4; i++) {
            int idx = tid + i * 256;
            int row = idx >> 3;
            int c4  = idx & 7;
            if (ATERMS == 2) {
                uint2 hi, lo; split4h(paf[i], hi, lo);
                *(uint2*)(base + row * RSB + c4 * 8) = hi;
                *(uint2*)(base + ABYTES + row * RSB + c4 * 8) = lo;
            } else {
                *(uint2*)(base + row * RSB + c4 * 8) = pack4h(paf[i]);
            }
        }
    };

    auto MMA = [&](int st) {
        const uint32_t aA = aAddr0 + st * STAGE;
        const uint32_t bA = bAddr0 + st * STAGE;
        #pragma unroll
        for (int ks = 0; ks < 2; ks++) {
            const uint32_t kOff = ks * 32;
            uint32_t ah[2][4], al[2][4];
            #pragma unroll
            for (int i = 0; i < 2; i++) {
                uint32_t aa = aA + i * 16 * RSB + kOff;
                LDSM_X4(ah[i][0], ah[i][1], ah[i][2], ah[i][3], aa);
                if (ATERMS == 2)
                    LDSM_X4(al[i][0], al[i][1], al[i][2], al[i][3], aa + ABYTES);
            }
            #pragma unroll
            for (int jp = 0; jp < NJ / 2; jp++) {
                uint32_t bb = bA + jp * 16 * RSB + kOff;
                uint32_t bh0, bh1, bh2, bh3;
                LDSM_X4(bh0, bh1, bh2, bh3, bb);
                #pragma unroll
                for (int i = 0; i < 2; i++) {
                    mma16816h(acc[i][2 * jp],     ah[i], bh0, bh1);
                    mma16816h(acc[i][2 * jp + 1], ah[i], bh2, bh3);
                    if (ATERMS == 2) {
                        mma16816h(acc[i][2 * jp],     al[i], bh0, bh1);
                        mma16816h(acc[i][2 * jp + 1], al[i], bh2, bh3);
                    }
                }
            }
        }
    };

    // ---- prologue ----
    if (AHL) cpA(0, 0); else ldA(0);
    cpB(0, 0);
    CP_COMMIT();

    // ---- mainloop ----
    for (int t = 0; t < NT; t++) {
        const int st = t & 1;
        if (!AHL) stsA(st);
        if (t + 1 < NT) {
            const int sn = (t + 1) & 1;
            if (AHL) cpA(t + 1, sn); else ldA(t + 1);
            cpB(t + 1, sn);
        }
        CP_COMMIT();
        if (t + 1 < NT) { CP_WAIT(1); } else { CP_WAIT(0); }
        __syncthreads();
        MMA(st);
        __syncthreads();
    }

    // ---- epilogue ----
    const int rBase = rowBase + warpM + (lid >> 2);
    const int cOff  = warpN + (lid & 3) * 2;
    #pragma unroll
    for (int i = 0; i < 2; i++) {
        #pragma unroll
        for (int j = 0; j < NJ; j++) {
            int cl = cOff + j * 8;
            int gc = colBase + cl;
            if (gc >= Mcols) continue;
            float2 bb = *(const float2*)(sm + OFF_BS + cl * 4);
            int r0 = rBase + i * 16;
            int r1 = r0 + 8;
            float2 v0, v1;
            v0.x = acc[i][j][0] + bb.x; v0.y = acc[i][j][1] + bb.y;
            v1.x = acc[i][j][2] + bb.x; v1.y = acc[i][j][3] + bb.y;
            if (RELU) {
                v0.x = fmaxf(v0.x, 0.f); v0.y = fmaxf(v0.y, 0.f);
                v1.x = fmaxf(v1.x, 0.f); v1.y = fmaxf(v1.y, 0.f);
            }
            __half2 q0 = __floats2half2_rn(v0.x, v0.y);
            __half2 q1 = __floats2half2_rn(v1.x, v1.y);
            if (OUTMODE == 3) {
                if (r0 < Nrows) *(uint32_t*)(Chalf + (size_t)r0 * Mcols + gc) = *(uint32_t*)&q0;
                if (r1 < Nrows) *(uint32_t*)(Chalf + (size_t)r1 * Mcols + gc) = *(uint32_t*)&q1;
            } else {   // OUTMODE == 4
                if (r0 < Nrows) {
                    *(float2*)(C + (size_t)r0 * Mcols + gc) = v0;
                    *(uint32_t*)(Chalf  + (size_t)r0 * Mcols + gc) = *(uint32_t*)&q0;
                    *(uint32_t*)(Chalf2 + (size_t)r0 * Mcols + gc) = *(uint32_t*)&q0;
                }
                if (r1 < Nrows) {
                    *(float2*)(C + (size_t)r1 * Mcols + gc) = v1;
                    *(uint32_t*)(Chalf  + (size_t)r1 * Mcols + gc) = *(uint32_t*)&q1;
                    *(uint32_t*)(Chalf2 + (size_t)r1 * Mcols + gc) = *(uint32_t*)&q1;
                }
            }
        }
    }
}

// ---------------- SpMM power-iteration step, fp16 iterate + fp16 h-term ----------------
#define SPH_T 320

template<int FINAL>
__global__ __launch_bounds__(SPH_T)
void spmm_h(const uint4* __restrict__ vh,     // fp16 iterate: 5 uint4 per row
            const uint4* __restrict__ hh,     // fp16 h: 5 uint4 per row (iters 0..8)
            const float4* __restrict__ hf,    // fp32 h (final iter)
            uint4* __restrict__ dsth,         // fp16 out (FINAL=0)
            float4* __restrict__ dstf)        // fp32 out (FINAL=1)
{
    int t = blockIdx.x * SPH_T + threadIdx.x;
    int r = t / 5;
    int f = t - r * 5;
    if (r >= N_NODES) return;

    const int s = g_rowstart[r];
    const int e = g_rowstart[r + 1];

    float a[8];
    #pragma unroll
    for (int j = 0; j < 8; j++) a[j] = 0.0f;

    int i = s;
    for (; i + 4 <= e; i += 4) {
        int c0 = g_cols[i + 0], c1 = g_cols[i + 1];
        int c2 = g_cols[i + 2], c3 = g_cols[i + 3];
        uint4 p0 = __ldg(vh + (size_t)c0 * 5 + f);
        uint4 p1 = __ldg(vh + (size_t)c1 * 5 + f);
        uint4 p2 = __ldg(vh + (size_t)c2 * 5 + f);
        uint4 p3 = __ldg(vh + (size_t)c3 * 5 + f);
        acc8(a, p0); acc8(a, p1); acc8(a, p2); acc8(a, p3);
    }
    for (; i < e; i++) {
        uint4 p = __ldg(vh + (size_t)g_cols[i] * 5 + f);
        acc8(a, p);
    }

    // self-loop term
    {
        uint4 p = __ldg(vh + (size_t)r * 5 + f);
        acc8(a, p);
    }

    const float w = 0.5f * g_dinv[r];
    float hterm[8];
    if (FINAL) {
        float4 h0 = __ldg(hf + (size_t)r * 10 + f * 2);
        float4 h1 = __ldg(hf + (size_t)r * 10 + f * 2 + 1);
        hterm[0] = h0.x; hterm[1] = h0.y; hterm[2] = h0.z; hterm[3] = h0.w;
        hterm[4] = h1.x; hterm[5] = h1.y; hterm[6] = h1.z; hterm[7] = h1.w;
    } else {
        uint4 ph = __ldg(hh + (size_t)r * 5 + f);
        float2 q;
        q = __half22float2(*(__half2*)&ph.x); hterm[0] = q.x; hterm[1] = q.y;
        q = __half22float2(*(__half2*)&ph.y); hterm[2] = q.x; hterm[3] = q.y;
        q = __half22float2(*(__half2*)&ph.z); hterm[4] = q.x; hterm[5] = q.y;
        q = __half22float2(*(__half2*)&ph.w); hterm[6] = q.x; hterm[7] = q.y;
    }

    float o[8];
    #pragma unroll
    for (int j = 0; j < 8; j++) o[j] = w * a[j] + 0.5f * hterm[j];

    if (FINAL) {
        dstf[(size_t)r * 10 + f * 2]     = make_float4(o[0], o[1], o[2], o[3]);
        dstf[(size_t)r * 10 + f * 2 + 1] = make_float4(o[4], o[5], o[6], o[7]);
    } else {
        __half2 q0 = __floats2half2_rn(o[0], o[1]);
        __half2 q1 = __floats2half2_rn(o[2], o[3]);
        __half2 q2 = __floats2half2_rn(o[4], o[5]);
        __half2 q3 = __floats2half2_rn(o[6], o[7]);
        uint4 pk;
        pk.x = *(uint32_t*)&q0; pk.y = *(uint32_t*)&q1;
        pk.z = *(uint32_t*)&q2; pk.w = *(uint32_t*)&q3;
        dsth[(size_t)r * 5 + f] = pk;
    }
}

// ---------------- host ----------------
extern "C" void kernel_launch(void* const* d_in, const int* in_sizes, int n_in,
                              void* d_out, int out_size)
{
    const float* x  = (const float*)d_in[0];
    const int*   ei = (const int*)  d_in[1];
    const float* W1 = (const float*)d_in[2];
    const float* b1 = (const float*)d_in[3];
    const float* W2 = (const float*)d_in[4];
    const float* b2 = (const float*)d_in[5];
    const float* W3 = (const float*)d_in[6];
    const float* b3 = (const float*)d_in[7];
    float* out = (float*)d_out;

    const int* rows = ei;
    const int* cols = ei + N_EDGES;

    void *p;
    float *h1, *h2, *h, *vA, *vB;
    __half *w1h, *w2h, *w3h, *hh;
    cudaGetSymbolAddress(&p, g_h1);  h1 = (float*)p;
    cudaGetSymbolAddress(&p, g_h2);  h2 = (float*)p;
    cudaGetSymbolAddress(&p, g_h);   h  = (float*)p;
    cudaGetSymbolAddress(&p, g_vA);  vA = (float*)p;
    cudaGetSymbolAddress(&p, g_vB);  vB = (float*)p;
    cudaGetSymbolAddress(&p, g_hh);  hh = (__half*)p;
    cudaGetSymbolAddress(&p, g_w1h); w1h = (__half*)p;
    cudaGetSymbolAddress(&p, g_w2h); w2h = (__half*)p;
    cudaGetSymbolAddress(&p, g_w3h); w3h = (__half*)p;

    __half* h1h = (__half*)h1;   // single-term fp16 h1
    __half* h2h = (__half*)h2;   // single-term fp16 h2

    // side stream + events for CSR/W-conv overlap
    cudaStream_t s1;
    cudaStreamCreateWithFlags(&s1, cudaStreamNonBlocking);
    cudaEvent_t evFork, evJoin, evW;
    cudaEventCreateWithFlags(&evFork, cudaEventDisableTiming);
    cudaEventCreateWithFlags(&evJoin, cudaEventDisableTiming);
    cudaEventCreateWithFlags(&evW, cudaEventDisableTiming);

    // ---- fork: w2/w3 conv + CSR build on side stream ----
    cudaEventRecord(evFork, 0);
    cudaStreamWaitEvent(s1, evFork, 0);
    conv_w<<<(NHID * NHID   + 255) / 256, 256, 0, s1>>>(W2, w2h, NHID * NHID);
    conv_w<<<(NCLASS * NHID + 255) / 256, 256, 0, s1>>>(W3, w3h, NCLASS * NHID);
    cudaEventRecord(evW, s1);
    zero_counts  <<<(N_NODES + 255) / 256, 256, 0, s1>>>();
    count_deg    <<<(N_EDGES + 255) / 256, 256, 0, s1>>>(rows);
    compute_dinv <<<(N_NODES + 255) / 256, 256, 0, s1>>>();
    scan_blocks  <<<NBLK, SCAN_T, 0, s1>>>();
    scan_offsets <<<1, 32, 0, s1>>>();
    scan_add     <<<NBLK, SCAN_T, 0, s1>>>();
    scatter_edges<<<(N_EDGES + 255) / 256, 256, 0, s1>>>(rows, cols);
    cudaEventRecord(evJoin, s1);

    // ---- main stream: w1 conv + GEMM chain ----
    conv_w<<<(NHID * NFEAT + 255) / 256, 256>>>(W1, w1h, NHID * NFEAT);

    const int STG1    = 128 * RSB + 128 * RSB;           // 20480 (ATERMS=1, BN=128)
    const int STG64_1 = 128 * RSB + 64 * RSB;            // 15360 (ATERMS=1, BN=64)
    const int SMEM_1    = 2 * STG1 + 128 * 4;            // 41472
    const int SMEM_64_1 = 2 * STG64_1 + 64 * 4;          // 30976
    cudaFuncSetAttribute((const void*)gemm_hmma<128, 1, 0, 3, 1>,
                         cudaFuncAttributeMaxDynamicSharedMemorySize, SMEM_1);
    cudaFuncSetAttribute((const void*)gemm_hmma<128, 1, 1, 3, 1>,
                         cudaFuncAttributeMaxDynamicSharedMemorySize, SMEM_1);
    cudaFuncSetAttribute((const void*)gemm_hmma<64, 0, 1, 4, 1>,
                         cudaFuncAttributeMaxDynamicSharedMemorySize, SMEM_64_1);

    const int MG = (N_NODES + 127) / 128;   // 782
    // GEMM1: A = fp16(x) single term; OUT = single fp16 h1
    gemm_hmma<128, 1, 0, 3, 1><<<dim3(2, MG), 256, SMEM_1>>>(
        x, nullptr, nullptr, w1h, b1, nullptr, h1h, nullptr,
        N_NODES, NHID, NFEAT);

    // GEMM2: A = fp16 h1 single term; OUT = single fp16 h2
    cudaStreamWaitEvent(0, evW, 0);
    gemm_hmma<128, 1, 1, 3, 1><<<dim3(2, MG), 256, SMEM_1>>>(
        nullptr, h1h, nullptr, w2h, b2, nullptr, h2h, nullptr,
        N_NODES, NHID, NHID);
    // GEMM3: A = fp16 h2 single term; emits fp32 h + fp16 v0 + fp16 hh
    gemm_hmma<64, 0, 1, 4, 1><<<dim3(1, MG), 256, SMEM_64_1>>>(
        nullptr, h2h, nullptr, w3h, b3, h, (__half*)vA, hh,
        N_NODES, NCLASS, NHID);

    // ---- join: CSR must be done before propagation ----
    cudaStreamWaitEvent(0, evJoin, 0);

    // ---- 10 power iterations (fp16 iterate + fp16 h-term; fp32 final) ----
    const int SP_G = (N_NODES * 5 + SPH_T - 1) / SPH_T;   // 1563
    const uint4* src = (const uint4*)vA;
    for (int it = 0; it < 9; it++) {
        uint4* dst = (uint4*)((it & 1) ? vA : vB);
        spmm_h<0><<<SP_G, SPH_T>>>(src, (const uint4*)hh, nullptr, dst, nullptr);
        src = dst;
    }
    spmm_h<1><<<SP_G, SPH_T>>>(src, nullptr, (const float4*)h, nullptr, (float4*)out);
}